// round 4
// baseline (speedup 1.0000x reference)
#include <cuda_runtime.h>
#include <math.h>

#define BB   4
#define NNq  1536
#define CC   512
#define HH   8
#define DD   64
#define HID  1024
#define ROWS (BB*NNq)   // 6144

// ---------------- scratch (static device globals; no allocation) ----------------
__device__ float g_h  [ROWS*CC];        // ln1 output
__device__ float g_qkv[ROWS*3*CC];      // qkv projection
__device__ float g_qe [BB*HH*NNq*DD];   // effective (shift-combined, pre-scaled) Q
__device__ float g_kt [BB*HH*NNq*DD];   // K  (B,H,N,d)
__device__ float g_vt [BB*HH*NNq*DD];   // V  (B,H,N,d)
__device__ float g_x2 [ROWS*CC];        // x + attn_out
__device__ float g_h2 [ROWS*CC];        // ln2 output
__device__ float g_act[ROWS*HID];       // gelu(fc1)

__device__ __forceinline__ float gelu_exact(float v) {
    return 0.5f * v * (1.0f + erff(v * 0.70710678118654752440f));
}

// ---------------- LayerNorm: one block (128 thr) per row of 512 ----------------
__global__ __launch_bounds__(128) void ln_kernel(
    const float* __restrict__ x, const float* __restrict__ g,
    const float* __restrict__ b, float* __restrict__ out)
{
    int row = blockIdx.x;
    int t = threadIdx.x;                   // 128 threads, 4 floats each
    const float4* xr = (const float4*)(x + (size_t)row * CC);
    float4 v = xr[t];
    float s  = v.x + v.y + v.z + v.w;
    float sq = v.x*v.x + v.y*v.y + v.z*v.z + v.w*v.w;
    #pragma unroll
    for (int o = 16; o; o >>= 1) {
        s  += __shfl_xor_sync(0xffffffffu, s,  o);
        sq += __shfl_xor_sync(0xffffffffu, sq, o);
    }
    __shared__ float rs[4], rq[4];
    int w = t >> 5;
    if ((t & 31) == 0) { rs[w] = s; rq[w] = sq; }
    __syncthreads();
    s  = rs[0] + rs[1] + rs[2] + rs[3];
    sq = rq[0] + rq[1] + rq[2] + rq[3];
    float mean = s * (1.0f / CC);
    float var  = sq * (1.0f / CC) - mean * mean;
    float rstd = rsqrtf(var + 1e-5f);
    float4 gv = ((const float4*)g)[t];
    float4 bv = ((const float4*)b)[t];
    float4 o4;
    o4.x = (v.x - mean) * rstd * gv.x + bv.x;
    o4.y = (v.y - mean) * rstd * gv.y + bv.y;
    o4.z = (v.z - mean) * rstd * gv.z + bv.z;
    o4.w = (v.w - mean) * rstd * gv.w + bv.w;
    ((float4*)(out + (size_t)row * CC))[t] = o4;
}

// ---------------- SGEMM: 128x128 tile, K-step 16, 256 threads, 8x8 micro ----------------
// EPI: 0 = bias only, 1 = bias + exact GELU, 2 = bias + residual add
template<int EPI>
__global__ __launch_bounds__(256) void gemm_kernel(
    const float* __restrict__ A, const float* __restrict__ B,
    const float* __restrict__ bias, const float* __restrict__ resid,
    float* __restrict__ C, int M, int Nn, int K)
{
    __shared__ __align__(16) float As[16][132];   // transposed: [k][m]
    __shared__ __align__(16) float Bs[16][132];   // [k][n]
    int tid = threadIdx.x;
    int tx = tid & 15, ty = tid >> 4;
    int bm = blockIdx.y * 128, bn = blockIdx.x * 128;

    float acc[8][8];
    #pragma unroll
    for (int i = 0; i < 8; i++)
        #pragma unroll
        for (int j = 0; j < 8; j++) acc[i][j] = 0.f;

    for (int k0 = 0; k0 < K; k0 += 16) {
        #pragma unroll
        for (int l = 0; l < 2; l++) {
            int idx = tid + l * 256;
            int r = idx >> 2, cg = idx & 3;
            float4 a = *(const float4*)(A + (size_t)(bm + r) * K + k0 + cg * 4);
            As[cg*4+0][r] = a.x; As[cg*4+1][r] = a.y;
            As[cg*4+2][r] = a.z; As[cg*4+3][r] = a.w;
        }
        #pragma unroll
        for (int l = 0; l < 2; l++) {
            int idx = tid + l * 256;
            int r = idx >> 5, cg = idx & 31;
            *(float4*)&Bs[r][cg*4] = *(const float4*)(B + (size_t)(k0 + r) * Nn + bn + cg * 4);
        }
        __syncthreads();
        #pragma unroll
        for (int kk = 0; kk < 16; kk++) {
            float a[8], bv[8];
            *(float4*)&a[0]  = *(float4*)&As[kk][ty*4];
            *(float4*)&a[4]  = *(float4*)&As[kk][64 + ty*4];
            *(float4*)&bv[0] = *(float4*)&Bs[kk][tx*4];
            *(float4*)&bv[4] = *(float4*)&Bs[kk][64 + tx*4];
            #pragma unroll
            for (int i = 0; i < 8; i++)
                #pragma unroll
                for (int j = 0; j < 8; j++)
                    acc[i][j] += a[i] * bv[j];
        }
        __syncthreads();
    }

    float bb[8];
    *(float4*)&bb[0] = *(const float4*)(bias + bn + tx*4);
    *(float4*)&bb[4] = *(const float4*)(bias + bn + 64 + tx*4);

    #pragma unroll
    for (int i = 0; i < 8; i++) {
        int ri = bm + ((i < 4) ? (ty*4 + i) : (64 + ty*4 + i - 4));
        #pragma unroll
        for (int half = 0; half < 2; half++) {
            int cj = bn + half * 64 + tx * 4;
            float v[4];
            #pragma unroll
            for (int j = 0; j < 4; j++) {
                float t = acc[i][half*4 + j] + bb[half*4 + j];
                if (EPI == 1) t = gelu_exact(t);
                v[j] = t;
            }
            if (EPI == 2) {
                float4 rr = *(const float4*)(resid + (size_t)ri * Nn + cj);
                v[0] += rr.x; v[1] += rr.y; v[2] += rr.z; v[3] += rr.w;
            }
            *(float4*)(C + (size_t)ri * Nn + cj) = make_float4(v[0], v[1], v[2], v[3]);
        }
    }
}

// ---------------- rearrange: build effective Q (segment shift folded in), K, V ----------------
// q'_n = (q_n + 0.5 q_{n-S} + 0.25 q_{n-2S}) * d^{-1/2}
__global__ __launch_bounds__(256) void rearrange_kernel()
{
    int flat = blockIdx.x * blockDim.x + threadIdx.x;   // float4 index, 786432 total
    int d4 = flat & 15;
    int n  = (flat >> 4) % NNq;
    int hb = (flat >> 4) / NNq;           // b*H + h
    int h = hb & 7, b = hb >> 3;
    int row = b * NNq + n;
    int c4  = (h * 64 + d4 * 4) >> 2;     // float4 col within 1536-wide row

    const float4* qkv4 = (const float4*)g_qkv;
    float4 q = qkv4[(size_t)row * 384 + c4];
    if (n >= 512) {
        float4 t = qkv4[(size_t)(row - 512) * 384 + c4];
        q.x += 0.5f * t.x; q.y += 0.5f * t.y; q.z += 0.5f * t.z; q.w += 0.5f * t.w;
    }
    if (n >= 1024) {
        float4 t = qkv4[(size_t)(row - 1024) * 384 + c4];
        q.x += 0.25f * t.x; q.y += 0.25f * t.y; q.z += 0.25f * t.z; q.w += 0.25f * t.w;
    }
    q.x *= 0.125f; q.y *= 0.125f; q.z *= 0.125f; q.w *= 0.125f;   // 1/sqrt(64)
    ((float4*)g_qe)[flat] = q;
    ((float4*)g_kt)[flat] = qkv4[(size_t)row * 384 + 128 + c4];
    ((float4*)g_vt)[flat] = qkv4[(size_t)row * 384 + 256 + c4];
}

// ---------------- flash attention: BQ=64, BK=64, d=64, 256 threads, 4x4 micro ----------------
// writes x2 = x + attn_out directly
__global__ __launch_bounds__(256) void attn_kernel(
    const float* __restrict__ x, float* __restrict__ x2)
{
    extern __shared__ __align__(16) float sm[];
    float* Qs  = sm;                       // [64][64]
    float* KsT = sm + 4096;                // [64][65]   d-major (transposed)
    float* Vs  = sm + 4096 + 4160;         // [64][64]
    float* Ps  = sm + 4096 + 4160 + 4096;  // [64][68]

    int tid = threadIdx.x;
    int tx = tid & 15, ty = tid >> 4;
    int bh = blockIdx.y;
    int q0 = blockIdx.x * 64;
    const float* Q = g_qe + (size_t)bh * NNq * DD + (size_t)q0 * DD;
    const float* K = g_kt + (size_t)bh * NNq * DD;
    const float* V = g_vt + (size_t)bh * NNq * DD;

    #pragma unroll
    for (int l = 0; l < 4; l++) {
        int idx = tid + l * 256;
        ((float4*)Qs)[idx] = ((const float4*)Q)[idx];
    }

    float m_run[4], l_run[4], oacc[4][4];
    #pragma unroll
    for (int i = 0; i < 4; i++) {
        m_run[i] = -3.0e38f; l_run[i] = 0.f;
        #pragma unroll
        for (int j = 0; j < 4; j++) oacc[i][j] = 0.f;
    }

    for (int kt = 0; kt < NNq / 64; kt++) {
        __syncthreads();   // previous iter's PV readers done before overwriting K/V
        const float4* Kg = (const float4*)(K + (size_t)kt * 64 * DD);
        const float4* Vg = (const float4*)(V + (size_t)kt * 64 * DD);
        #pragma unroll
        for (int l = 0; l < 4; l++) {
            int idx = tid + l * 256;
            int r = idx >> 4, cg = idx & 15;
            float4 kv = Kg[idx];
            KsT[(cg*4+0)*65 + r] = kv.x;
            KsT[(cg*4+1)*65 + r] = kv.y;
            KsT[(cg*4+2)*65 + r] = kv.z;
            KsT[(cg*4+3)*65 + r] = kv.w;
            ((float4*)Vs)[idx] = Vg[idx];
        }
        __syncthreads();

        // S = Q' K^T  (scale already folded into Q')
        float s[4][4];
        #pragma unroll
        for (int i = 0; i < 4; i++)
            #pragma unroll
            for (int j = 0; j < 4; j++) s[i][j] = 0.f;
        #pragma unroll
        for (int d4 = 0; d4 < 16; d4++) {
            float qa[4][4];
            #pragma unroll
            for (int i = 0; i < 4; i++) {
                float4 t = *(float4*)&Qs[(ty*4 + i) * 64 + d4 * 4];
                qa[i][0] = t.x; qa[i][1] = t.y; qa[i][2] = t.z; qa[i][3] = t.w;
            }
            #pragma unroll
            for (int dd = 0; dd < 4; dd++) {
                float kb[4];
                #pragma unroll
                for (int j = 0; j < 4; j++) kb[j] = KsT[(d4*4 + dd) * 65 + tx*4 + j];
                #pragma unroll
                for (int i = 0; i < 4; i++)
                    #pragma unroll
                    for (int j = 0; j < 4; j++)
                        s[i][j] += qa[i][dd] * kb[j];
            }
        }

        // online softmax: row q owned by the 16 tx-lanes of its ty group
        #pragma unroll
        for (int i = 0; i < 4; i++) {
            float mx = fmaxf(fmaxf(s[i][0], s[i][1]), fmaxf(s[i][2], s[i][3]));
            #pragma unroll
            for (int m = 1; m < 16; m <<= 1)
                mx = fmaxf(mx, __shfl_xor_sync(0xffffffffu, mx, m));
            float mnew = fmaxf(m_run[i], mx);
            float corr = __expf(m_run[i] - mnew);
            float sum = 0.f;
            #pragma unroll
            for (int j = 0; j < 4; j++) {
                float p = __expf(s[i][j] - mnew);
                s[i][j] = p; sum += p;
            }
            #pragma unroll
            for (int m = 1; m < 16; m <<= 1)
                sum += __shfl_xor_sync(0xffffffffu, sum, m);
            l_run[i] = l_run[i] * corr + sum;
            m_run[i] = mnew;
            #pragma unroll
            for (int j = 0; j < 4; j++) oacc[i][j] *= corr;
            *(float4*)&Ps[(ty*4 + i) * 68 + tx*4] = make_float4(s[i][0], s[i][1], s[i][2], s[i][3]);
        }
        __syncthreads();

        // O += P @ V
        #pragma unroll
        for (int k4 = 0; k4 < 16; k4++) {
            float pa[4][4];
            #pragma unroll
            for (int i = 0; i < 4; i++) {
                float4 t = *(float4*)&Ps[(ty*4 + i) * 68 + k4 * 4];
                pa[i][0] = t.x; pa[i][1] = t.y; pa[i][2] = t.z; pa[i][3] = t.w;
            }
            #pragma unroll
            for (int kk = 0; kk < 4; kk++) {
                float4 vv = *(float4*)&Vs[(k4*4 + kk) * 64 + tx*4];
                float vb[4] = {vv.x, vv.y, vv.z, vv.w};
                #pragma unroll
                for (int i = 0; i < 4; i++)
                    #pragma unroll
                    for (int j = 0; j < 4; j++)
                        oacc[i][j] += pa[i][kk] * vb[j];
            }
        }
    }

    int b = bh >> 3, h = bh & 7;
    #pragma unroll
    for (int i = 0; i < 4; i++) {
        float inv = 1.0f / l_run[i];
        int n = q0 + ty*4 + i;
        size_t off = ((size_t)(b * NNq + n)) * CC + h * 64 + tx * 4;
        float4 xr = *(const float4*)(x + off);
        *(float4*)(x2 + off) = make_float4(
            xr.x + oacc[i][0] * inv, xr.y + oacc[i][1] * inv,
            xr.z + oacc[i][2] * inv, xr.w + oacc[i][3] * inv);
    }
}

// ---------------- host ----------------
extern "C" void kernel_launch(void* const* d_in, const int* in_sizes, int n_in,
                              void* d_out, int out_size)
{
    const float* x     = (const float*)d_in[0];
    const float* ln1_g = (const float*)d_in[1];
    const float* ln1_b = (const float*)d_in[2];
    const float* qkv_w = (const float*)d_in[3];
    const float* qkv_b = (const float*)d_in[4];
    const float* ln2_g = (const float*)d_in[5];
    const float* ln2_b = (const float*)d_in[6];
    const float* fc1_w = (const float*)d_in[7];
    const float* fc1_b = (const float*)d_in[8];
    const float* fc2_w = (const float*)d_in[9];
    const float* fc2_b = (const float*)d_in[10];
    float* out = (float*)d_out;

    float *p_h, *p_qkv, *p_x2, *p_h2, *p_act;
    cudaGetSymbolAddress((void**)&p_h,   g_h);
    cudaGetSymbolAddress((void**)&p_qkv, g_qkv);
    cudaGetSymbolAddress((void**)&p_x2,  g_x2);
    cudaGetSymbolAddress((void**)&p_h2,  g_h2);
    cudaGetSymbolAddress((void**)&p_act, g_act);

    const int ATTN_SMEM = (4096 + 65*64 + 4096 + 68*64) * 4;   // 66816 B
    cudaFuncSetAttribute(attn_kernel, cudaFuncAttributeMaxDynamicSharedMemorySize, ATTN_SMEM);

    // 1. LN1
    ln_kernel<<<ROWS, 128>>>(x, ln1_g, ln1_b, p_h);
    // 2. QKV projection: (6144x512) @ (512x1536)
    gemm_kernel<0><<<dim3(1536/128, ROWS/128), 256>>>(p_h, qkv_w, qkv_b, nullptr, p_qkv, ROWS, 1536, 512);
    // 3. effective-Q / K / V rearrange
    rearrange_kernel<<<(BB*HH*NNq*DD/4)/256, 256>>>();
    // 4. flash attention + residual into x2
    attn_kernel<<<dim3(NNq/64, BB*HH), 256, ATTN_SMEM>>>(x, p_x2);
    // 5. LN2
    ln_kernel<<<ROWS, 128>>>(p_x2, ln2_g, ln2_b, p_h2);
    // 6. FC1 + GELU: (6144x512) @ (512x1024)
    gemm_kernel<1><<<dim3(HID/128, ROWS/128), 256>>>(p_h2, fc1_w, fc1_b, nullptr, p_act, ROWS, HID, 512);
    // 7. FC2 + residual: (6144x1024) @ (1024x512) + x2 -> out
    gemm_kernel<2><<<dim3(CC/128, ROWS/128), 256>>>(p_act, fc2_w, fc2_b, p_x2, out, ROWS, CC, HID);
}

// round 7
// speedup vs baseline: 1.0506x; 1.0506x over previous
#include <cuda_runtime.h>
#include <math.h>

#define BB   4
#define NNq  1536
#define CC   512
#define HH   8
#define DD   64
#define HID  1024
#define ROWS (BB*NNq)   // 6144
#define NT   (NNq/64)   // 24 key tiles

// ---------------- scratch (static device globals; no allocation) ----------------
__device__ float g_h  [ROWS*CC];
__device__ float g_qkv[ROWS*3*CC];
__device__ float g_qe [BB*HH*NNq*DD];
__device__ float g_kt [BB*HH*NNq*DD];
__device__ float g_vt [BB*HH*NNq*DD];
__device__ float g_x2 [ROWS*CC];
__device__ float g_h2 [ROWS*CC];
__device__ float g_act[ROWS*HID];

typedef unsigned long long u64;

__device__ __forceinline__ u64 pk2(float lo, float hi) {
    u64 r; asm("mov.b64 %0, {%1, %2};" : "=l"(r) : "f"(lo), "f"(hi)); return r;
}
__device__ __forceinline__ void upk2(u64 v, float& lo, float& hi) {
    asm("mov.b64 {%0, %1}, %2;" : "=f"(lo), "=f"(hi) : "l"(v));
}
__device__ __forceinline__ u64 ffma2(u64 a, u64 b, u64 c) {
    u64 d; asm("fma.rn.f32x2 %0, %1, %2, %3;" : "=l"(d) : "l"(a), "l"(b), "l"(c)); return d;
}
__device__ __forceinline__ u64 fmul2(u64 a, u64 b) {
    u64 d; asm("mul.rn.f32x2 %0, %1, %2;" : "=l"(d) : "l"(a), "l"(b)); return d;
}

__device__ __forceinline__ float gelu_exact(float v) {
    return 0.5f * v * (1.0f + erff(v * 0.70710678118654752440f));
}

// ---------------- LayerNorm: one block (128 thr) per row of 512 ----------------
__global__ __launch_bounds__(128) void ln_kernel(
    const float* __restrict__ x, const float* __restrict__ g,
    const float* __restrict__ b, float* __restrict__ out)
{
    int row = blockIdx.x;
    int t = threadIdx.x;
    const float4* xr = (const float4*)(x + (size_t)row * CC);
    float4 v = xr[t];
    float s  = v.x + v.y + v.z + v.w;
    float sq = v.x*v.x + v.y*v.y + v.z*v.z + v.w*v.w;
    #pragma unroll
    for (int o = 16; o; o >>= 1) {
        s  += __shfl_xor_sync(0xffffffffu, s,  o);
        sq += __shfl_xor_sync(0xffffffffu, sq, o);
    }
    __shared__ float rs[4], rq[4];
    int w = t >> 5;
    if ((t & 31) == 0) { rs[w] = s; rq[w] = sq; }
    __syncthreads();
    s  = rs[0] + rs[1] + rs[2] + rs[3];
    sq = rq[0] + rq[1] + rq[2] + rq[3];
    float mean = s * (1.0f / CC);
    float var  = sq * (1.0f / CC) - mean * mean;
    float rstd = rsqrtf(var + 1e-5f);
    float4 gv = ((const float4*)g)[t];
    float4 bv = ((const float4*)b)[t];
    float4 o4;
    o4.x = (v.x - mean) * rstd * gv.x + bv.x;
    o4.y = (v.y - mean) * rstd * gv.y + bv.y;
    o4.z = (v.z - mean) * rstd * gv.z + bv.z;
    o4.w = (v.w - mean) * rstd * gv.w + bv.w;
    ((float4*)(out + (size_t)row * CC))[t] = o4;
}

// ---------------- SGEMM: 128x128 tile, double-buffered K-step 16, FFMA2 ----------------
// EPI: 0 = bias only, 1 = bias + exact GELU, 2 = bias + residual add
template<int EPI>
__global__ __launch_bounds__(256, 2) void gemm_kernel(
    const float* __restrict__ A, const float* __restrict__ B,
    const float* __restrict__ bias, const float* __restrict__ resid,
    float* __restrict__ C, int M, int Nn, int K)
{
    __shared__ __align__(16) float As[2][16][132];   // [k][m] (transposed)
    __shared__ __align__(16) float Bs[2][16][132];   // [k][n]
    int tid = threadIdx.x;
    int tx = tid & 15, ty = tid >> 4;
    int bm = blockIdx.y * 128, bn = blockIdx.x * 128;

    u64 acc[8][4];
    #pragma unroll
    for (int i = 0; i < 8; i++)
        #pragma unroll
        for (int j = 0; j < 4; j++) acc[i][j] = 0ull;

    float4 ra[2], rb[2];
    int ar[2], ac[2], br2[2], bc2[2];
    #pragma unroll
    for (int l = 0; l < 2; l++) {
        int idx = tid + l * 256;
        ar[l] = idx >> 2;  ac[l] = idx & 3;
        br2[l] = idx >> 5; bc2[l] = idx & 31;
    }

    // prologue: tile 0 -> smem buf 0; tile 1 held in regs
    #pragma unroll
    for (int l = 0; l < 2; l++) {
        ra[l] = *(const float4*)(A + (size_t)(bm + ar[l]) * K + ac[l] * 4);
        rb[l] = *(const float4*)(B + (size_t)br2[l] * Nn + bn + bc2[l] * 4);
    }
    #pragma unroll
    for (int l = 0; l < 2; l++) {
        As[0][ac[l]*4+0][ar[l]] = ra[l].x; As[0][ac[l]*4+1][ar[l]] = ra[l].y;
        As[0][ac[l]*4+2][ar[l]] = ra[l].z; As[0][ac[l]*4+3][ar[l]] = ra[l].w;
        *(float4*)&Bs[0][br2[l]][bc2[l]*4] = rb[l];
    }
    if (K > 16) {
        #pragma unroll
        for (int l = 0; l < 2; l++) {
            ra[l] = *(const float4*)(A + (size_t)(bm + ar[l]) * K + 16 + ac[l] * 4);
            rb[l] = *(const float4*)(B + (size_t)(16 + br2[l]) * Nn + bn + bc2[l] * 4);
        }
    }
    __syncthreads();

    int nst = K / 16, cur = 0;
    for (int t = 0; t < nst; t++) {
        #pragma unroll
        for (int kk = 0; kk < 16; kk++) {
            float a[8];
            *(float4*)&a[0] = *(float4*)&As[cur][kk][ty*4];
            *(float4*)&a[4] = *(float4*)&As[cur][kk][64 + ty*4];
            ulonglong2 b0 = *(ulonglong2*)&Bs[cur][kk][tx*4];
            ulonglong2 b1 = *(ulonglong2*)&Bs[cur][kk][64 + tx*4];
            u64 bp0 = b0.x, bp1 = b0.y, bp2 = b1.x, bp3 = b1.y;
            #pragma unroll
            for (int i = 0; i < 8; i++) {
                u64 ap = pk2(a[i], a[i]);
                acc[i][0] = ffma2(ap, bp0, acc[i][0]);
                acc[i][1] = ffma2(ap, bp1, acc[i][1]);
                acc[i][2] = ffma2(ap, bp2, acc[i][2]);
                acc[i][3] = ffma2(ap, bp3, acc[i][3]);
            }
        }
        if (t + 1 < nst) {
            int nb = 1 ^ cur;
            #pragma unroll
            for (int l = 0; l < 2; l++) {
                As[nb][ac[l]*4+0][ar[l]] = ra[l].x; As[nb][ac[l]*4+1][ar[l]] = ra[l].y;
                As[nb][ac[l]*4+2][ar[l]] = ra[l].z; As[nb][ac[l]*4+3][ar[l]] = ra[l].w;
                *(float4*)&Bs[nb][br2[l]][bc2[l]*4] = rb[l];
            }
            if (t + 2 < nst) {
                int k0 = (t + 2) * 16;
                #pragma unroll
                for (int l = 0; l < 2; l++) {
                    ra[l] = *(const float4*)(A + (size_t)(bm + ar[l]) * K + k0 + ac[l] * 4);
                    rb[l] = *(const float4*)(B + (size_t)(k0 + br2[l]) * Nn + bn + bc2[l] * 4);
                }
            }
        }
        __syncthreads();
        cur ^= 1;
    }

    float accf[8][8];
    #pragma unroll
    for (int i = 0; i < 8; i++)
        #pragma unroll
        for (int jp = 0; jp < 4; jp++)
            upk2(acc[i][jp], accf[i][jp*2], accf[i][jp*2+1]);

    float bb[8];
    *(float4*)&bb[0] = *(const float4*)(bias + bn + tx*4);
    *(float4*)&bb[4] = *(const float4*)(bias + bn + 64 + tx*4);

    #pragma unroll
    for (int i = 0; i < 8; i++) {
        int ri = bm + ((i < 4) ? (ty*4 + i) : (64 + ty*4 + i - 4));
        #pragma unroll
        for (int half = 0; half < 2; half++) {
            int cj = bn + half * 64 + tx * 4;
            float v[4];
            #pragma unroll
            for (int j = 0; j < 4; j++) {
                float tv = accf[i][half*4 + j] + bb[half*4 + j];
                if (EPI == 1) tv = gelu_exact(tv);
                v[j] = tv;
            }
            if (EPI == 2) {
                float4 rr = *(const float4*)(resid + (size_t)ri * Nn + cj);
                v[0] += rr.x; v[1] += rr.y; v[2] += rr.z; v[3] += rr.w;
            }
            *(float4*)(C + (size_t)ri * Nn + cj) = make_float4(v[0], v[1], v[2], v[3]);
        }
    }
}

// ---------------- rearrange: effective Q (shift folded), K, V ----------------
__global__ __launch_bounds__(256) void rearrange_kernel()
{
    int flat = blockIdx.x * blockDim.x + threadIdx.x;
    int d4 = flat & 15;
    int n  = (flat >> 4) % NNq;
    int hb = (flat >> 4) / NNq;
    int h = hb & 7, b = hb >> 3;
    int row = b * NNq + n;
    int c4  = (h * 64 + d4 * 4) >> 2;

    const float4* qkv4 = (const float4*)g_qkv;
    float4 q = qkv4[(size_t)row * 384 + c4];
    if (n >= 512) {
        float4 t = qkv4[(size_t)(row - 512) * 384 + c4];
        q.x += 0.5f * t.x; q.y += 0.5f * t.y; q.z += 0.5f * t.z; q.w += 0.5f * t.w;
    }
    if (n >= 1024) {
        float4 t = qkv4[(size_t)(row - 1024) * 384 + c4];
        q.x += 0.25f * t.x; q.y += 0.25f * t.y; q.z += 0.25f * t.z; q.w += 0.25f * t.w;
    }
    q.x *= 0.125f; q.y *= 0.125f; q.z *= 0.125f; q.w *= 0.125f;
    ((float4*)g_qe)[flat] = q;
    ((float4*)g_kt)[flat] = qkv4[(size_t)row * 384 + 128 + c4];
    ((float4*)g_vt)[flat] = qkv4[(size_t)row * 384 + 256 + c4];
}

// ---------------- flash attention: BQ=BK=64, double-buffered, FFMA2 ----------------
__device__ __forceinline__ void attn_ld_tile(
    const float* K, const float* V, int kt, int tid, float4* kreg, float4* vreg)
{
    const float4* Kg = (const float4*)(K + (size_t)kt * 64 * DD);
    const float4* Vg = (const float4*)(V + (size_t)kt * 64 * DD);
    #pragma unroll
    for (int l = 0; l < 4; l++) {
        kreg[l] = Kg[tid + l * 256];
        vreg[l] = Vg[tid + l * 256];
    }
}
__device__ __forceinline__ void attn_st_tile(
    float* KsT, float* Vs, int tid, const float4* kreg, const float4* vreg)
{
    #pragma unroll
    for (int l = 0; l < 4; l++) {
        int idx = tid + l * 256;
        int r = idx >> 4, cg = idx & 15;
        float4 kv = kreg[l];
        KsT[(cg*4+0)*68 + r] = kv.x;
        KsT[(cg*4+1)*68 + r] = kv.y;
        KsT[(cg*4+2)*68 + r] = kv.z;
        KsT[(cg*4+3)*68 + r] = kv.w;
        ((float4*)Vs)[idx] = vreg[l];
    }
}

__global__ __launch_bounds__(256, 2) void attn_kernel(
    const float* __restrict__ x, float* __restrict__ x2)
{
    extern __shared__ __align__(16) float sm[];
    float* Qs  = sm;                    // [64][64]          4096
    float* Ks0 = sm + 4096;             // [64 d][68 j]      4352
    float* Ks1 = Ks0 + 4352;
    float* Vs0 = Ks1 + 4352;            // [64][64]          4096
    float* Vs1 = Vs0 + 4096;
    float* Ps  = Vs1 + 4096;            // [64][68]          4352
    float* KsB[2] = {Ks0, Ks1};
    float* VsB[2] = {Vs0, Vs1};

    int tid = threadIdx.x;
    int tx = tid & 15, ty = tid >> 4;
    int bh = blockIdx.y;
    int q0 = blockIdx.x * 64;
    const float* Q = g_qe + (size_t)bh * NNq * DD + (size_t)q0 * DD;
    const float* K = g_kt + (size_t)bh * NNq * DD;
    const float* V = g_vt + (size_t)bh * NNq * DD;

    float4 kreg[4], vreg[4];
    // Q tile -> smem
    #pragma unroll
    for (int l = 0; l < 4; l++)
        ((float4*)Qs)[tid + l * 256] = ((const float4*)Q)[tid + l * 256];
    // tile 0 -> buf0, tile 1 held in regs
    attn_ld_tile(K, V, 0, tid, kreg, vreg);
    attn_st_tile(Ks0, Vs0, tid, kreg, vreg);
    attn_ld_tile(K, V, 1, tid, kreg, vreg);
    __syncthreads();

    float m_run[4], l_run[4];
    u64 oacc[4][2];
    #pragma unroll
    for (int i = 0; i < 4; i++) {
        m_run[i] = -3.0e38f; l_run[i] = 0.f;
        oacc[i][0] = 0ull; oacc[i][1] = 0ull;
    }

    int cur = 0;
    for (int kt = 0; kt < NT; kt++) {
        const float* KsT = KsB[cur];
        const float* Vs  = VsB[cur];

        // S = Q' K^T   (packed over j)
        u64 sP[4][2];
        #pragma unroll
        for (int i = 0; i < 4; i++) { sP[i][0] = 0ull; sP[i][1] = 0ull; }
        #pragma unroll
        for (int d4 = 0; d4 < 16; d4++) {
            float4 qv[4];
            #pragma unroll
            for (int i = 0; i < 4; i++)
                qv[i] = *(const float4*)&Qs[(ty*4 + i) * 64 + d4 * 4];
            #pragma unroll
            for (int dd = 0; dd < 4; dd++) {
                ulonglong2 kb = *(const ulonglong2*)&KsT[(d4*4 + dd) * 68 + tx*4];
                #pragma unroll
                for (int i = 0; i < 4; i++) {
                    float qs = (dd == 0) ? qv[i].x : (dd == 1) ? qv[i].y : (dd == 2) ? qv[i].z : qv[i].w;
                    u64 qp = pk2(qs, qs);
                    sP[i][0] = ffma2(qp, kb.x, sP[i][0]);
                    sP[i][1] = ffma2(qp, kb.y, sP[i][1]);
                }
            }
        }

        // online softmax (rows owned by the 16 tx lanes of each ty group)
        #pragma unroll
        for (int i = 0; i < 4; i++) {
            float s0, s1, s2, s3;
            upk2(sP[i][0], s0, s1);
            upk2(sP[i][1], s2, s3);
            float mx = fmaxf(fmaxf(s0, s1), fmaxf(s2, s3));
            #pragma unroll
            for (int m = 1; m < 16; m <<= 1)
                mx = fmaxf(mx, __shfl_xor_sync(0xffffffffu, mx, m));
            float mnew = fmaxf(m_run[i], mx);
            float corr = __expf(m_run[i] - mnew);
            float p0 = __expf(s0 - mnew), p1 = __expf(s1 - mnew);
            float p2 = __expf(s2 - mnew), p3 = __expf(s3 - mnew);
            float sum = p0 + p1 + p2 + p3;
            #pragma unroll
            for (int m = 1; m < 16; m <<= 1)
                sum += __shfl_xor_sync(0xffffffffu, sum, m);
            l_run[i] = l_run[i] * corr + sum;
            m_run[i] = mnew;
            u64 cp = pk2(corr, corr);
            oacc[i][0] = fmul2(oacc[i][0], cp);
            oacc[i][1] = fmul2(oacc[i][1], cp);
            *(float4*)&Ps[(ty*4 + i) * 68 + tx*4] = make_float4(p0, p1, p2, p3);
        }
        __syncthreads();   // Ps visible; all threads done with QK reads

        // O += P @ V  (packed over d)
        #pragma unroll
        for (int k4 = 0; k4 < 16; k4++) {
            float4 pv[4];
            #pragma unroll
            for (int i = 0; i < 4; i++)
                pv[i] = *(const float4*)&Ps[(ty*4 + i) * 68 + k4 * 4];
            #pragma unroll
            for (int kk = 0; kk < 4; kk++) {
                ulonglong2 vv = *(const ulonglong2*)&Vs[(k4*4 + kk) * 64 + tx*4];
                #pragma unroll
                for (int i = 0; i < 4; i++) {
                    float pvs = (kk == 0) ? pv[i].x : (kk == 1) ? pv[i].y : (kk == 2) ? pv[i].z : pv[i].w;
                    u64 pp = pk2(pvs, pvs);
                    oacc[i][0] = ffma2(pp, vv.x, oacc[i][0]);
                    oacc[i][1] = ffma2(pp, vv.y, oacc[i][1]);
                }
            }
        }

        if (kt + 1 < NT) {
            attn_st_tile(KsB[1 ^ cur], VsB[1 ^ cur], tid, kreg, vreg);
            if (kt + 2 < NT)
                attn_ld_tile(K, V, kt + 2, tid, kreg, vreg);
        }
        __syncthreads();   // next buffer ready; all done reading Vs/Ps this iter
        cur ^= 1;
    }

    int b = bh >> 3, h = bh & 7;
    #pragma unroll
    for (int i = 0; i < 4; i++) {
        float inv = 1.0f / l_run[i];
        float o0, o1, o2, o3;
        upk2(oacc[i][0], o0, o1);
        upk2(oacc[i][1], o2, o3);
        int n = q0 + ty*4 + i;
        size_t off = ((size_t)(b * NNq + n)) * CC + h * 64 + tx * 4;
        float4 xr = *(const float4*)(x + off);
        *(float4*)(x2 + off) = make_float4(
            xr.x + o0 * inv, xr.y + o1 * inv,
            xr.z + o2 * inv, xr.w + o3 * inv);
    }
}

// ---------------- host ----------------
extern "C" void kernel_launch(void* const* d_in, const int* in_sizes, int n_in,
                              void* d_out, int out_size)
{
    const float* x     = (const float*)d_in[0];
    const float* ln1_g = (const float*)d_in[1];
    const float* ln1_b = (const float*)d_in[2];
    const float* qkv_w = (const float*)d_in[3];
    const float* qkv_b = (const float*)d_in[4];
    const float* ln2_g = (const float*)d_in[5];
    const float* ln2_b = (const float*)d_in[6];
    const float* fc1_w = (const float*)d_in[7];
    const float* fc1_b = (const float*)d_in[8];
    const float* fc2_w = (const float*)d_in[9];
    const float* fc2_b = (const float*)d_in[10];
    float* out = (float*)d_out;

    float *p_h, *p_qkv, *p_x2, *p_h2, *p_act;
    cudaGetSymbolAddress((void**)&p_h,   g_h);
    cudaGetSymbolAddress((void**)&p_qkv, g_qkv);
    cudaGetSymbolAddress((void**)&p_x2,  g_x2);
    cudaGetSymbolAddress((void**)&p_h2,  g_h2);
    cudaGetSymbolAddress((void**)&p_act, g_act);

    const int ATTN_SMEM = (4096 + 2*4352 + 2*4096 + 4352) * 4;   // 101376 B
    cudaFuncSetAttribute(attn_kernel, cudaFuncAttributeMaxDynamicSharedMemorySize, ATTN_SMEM);

    // 1. LN1
    ln_kernel<<<ROWS, 128>>>(x, ln1_g, ln1_b, p_h);
    // 2. QKV projection
    gemm_kernel<0><<<dim3(1536/128, ROWS/128), 256>>>(p_h, qkv_w, qkv_b, nullptr, p_qkv, ROWS, 1536, 512);
    // 3. effective-Q / K / V rearrange
    rearrange_kernel<<<(BB*HH*NNq*DD/4)/256, 256>>>();
    // 4. flash attention + residual into x2
    attn_kernel<<<dim3(NNq/64, BB*HH), 256, ATTN_SMEM>>>(x, p_x2);
    // 5. LN2
    ln_kernel<<<ROWS, 128>>>(p_x2, ln2_g, ln2_b, p_h2);
    // 6. FC1 + GELU
    gemm_kernel<1><<<dim3(HID/128, ROWS/128), 256>>>(p_h2, fc1_w, fc1_b, nullptr, p_act, ROWS, HID, 512);
    // 7. FC2 + residual -> out
    gemm_kernel<2><<<dim3(CC/128, ROWS/128), 256>>>(p_act, fc2_w, fc2_b, p_x2, out, ROWS, CC, HID);
}

// round 9
// speedup vs baseline: 1.3731x; 1.3071x over previous
#include <cuda_runtime.h>
#include <math.h>
#include <stdint.h>

#define BB   4
#define NNq  1536
#define CC   512
#define HH   8
#define DD   64
#define HID  1024
#define ROWS (BB*NNq)   // 6144
#define NT   (NNq/64)   // 24 key tiles

// ---------------- scratch (static device globals; no allocation) ----------------
__device__ float g_h  [ROWS*CC];        // ln1 out
__device__ float g_qkv[ROWS*3*CC];
__device__ float g_qe [BB*HH*NNq*DD];
__device__ float g_kt [BB*HH*NNq*DD];
__device__ float g_vt [BB*HH*NNq*DD];
__device__ float g_x2 [ROWS*CC];
__device__ float g_h2 [ROWS*CC];        // ln2 out
__device__ float g_act[ROWS*HID];       // gelu(fc1)
__device__ float g_wq [1536*512];       // qkv_w^T [N][K]
__device__ float g_w1 [1024*512];       // fc1_w^T
__device__ float g_w2 [512*1024];       // fc2_w^T

typedef unsigned long long u64;

__device__ __forceinline__ u64 pk2(float lo, float hi) {
    u64 r; asm("mov.b64 %0, {%1, %2};" : "=l"(r) : "f"(lo), "f"(hi)); return r;
}
__device__ __forceinline__ void upk2(u64 v, float& lo, float& hi) {
    asm("mov.b64 {%0, %1}, %2;" : "=f"(lo), "=f"(hi) : "l"(v));
}
__device__ __forceinline__ u64 ffma2(u64 a, u64 b, u64 c) {
    u64 d; asm("fma.rn.f32x2 %0, %1, %2, %3;" : "=l"(d) : "l"(a), "l"(b), "l"(c)); return d;
}
__device__ __forceinline__ u64 fmul2(u64 a, u64 b) {
    u64 d; asm("mul.rn.f32x2 %0, %1, %2;" : "=l"(d) : "l"(a), "l"(b)); return d;
}
__device__ __forceinline__ float gelu_exact(float v) {
    return 0.5f * v * (1.0f + erff(v * 0.70710678118654752440f));
}

// tf32 mma: D(16x8) += A(16x8) * B(8x8), fp32 accum. Plain sm_80+ opcode (no 'a' target).
__device__ __forceinline__ void mma_tf32(float* c, const uint32_t* a, const uint32_t* b) {
    asm volatile("mma.sync.aligned.m16n8k8.row.col.f32.tf32.tf32.f32 "
        "{%0,%1,%2,%3}, {%4,%5,%6,%7}, {%8,%9}, {%0,%1,%2,%3};"
        : "+f"(c[0]), "+f"(c[1]), "+f"(c[2]), "+f"(c[3])
        : "r"(a[0]), "r"(a[1]), "r"(a[2]), "r"(a[3]), "r"(b[0]), "r"(b[1]));
}

// ---------------- LayerNorm: one block (128 thr) per row of 512 ----------------
__global__ __launch_bounds__(128) void ln_kernel(
    const float* __restrict__ x, const float* __restrict__ g,
    const float* __restrict__ b, float* __restrict__ out)
{
    int row = blockIdx.x;
    int t = threadIdx.x;
    const float4* xr = (const float4*)(x + (size_t)row * CC);
    float4 v = xr[t];
    float s  = v.x + v.y + v.z + v.w;
    float sq = v.x*v.x + v.y*v.y + v.z*v.z + v.w*v.w;
    #pragma unroll
    for (int o = 16; o; o >>= 1) {
        s  += __shfl_xor_sync(0xffffffffu, s,  o);
        sq += __shfl_xor_sync(0xffffffffu, sq, o);
    }
    __shared__ float rs[4], rq[4];
    int w = t >> 5;
    if ((t & 31) == 0) { rs[w] = s; rq[w] = sq; }
    __syncthreads();
    s  = rs[0] + rs[1] + rs[2] + rs[3];
    sq = rq[0] + rq[1] + rq[2] + rq[3];
    float mean = s * (1.0f / CC);
    float var  = sq * (1.0f / CC) - mean * mean;
    float rstd = rsqrtf(var + 1e-5f);
    float4 gv = ((const float4*)g)[t];
    float4 bv = ((const float4*)b)[t];
    float4 o4;
    o4.x = (v.x - mean) * rstd * gv.x + bv.x;
    o4.y = (v.y - mean) * rstd * gv.y + bv.y;
    o4.z = (v.z - mean) * rstd * gv.z + bv.z;
    o4.w = (v.w - mean) * rstd * gv.w + bv.w;
    ((float4*)(out + (size_t)row * CC))[t] = o4;
}

// ---------------- weight transpose: Wt[n][k] = W[k][n] (fp32) ----------------
__global__ __launch_bounds__(256) void transpose_kernel(
    const float* __restrict__ W, float* __restrict__ Wt, int K, int N)
{
    __shared__ float tile[32][33];
    int n0 = blockIdx.x * 32, k0 = blockIdx.y * 32;
    int tx = threadIdx.x & 31, ty = threadIdx.x >> 5;   // 32 x 8
    #pragma unroll
    for (int r = 0; r < 32; r += 8)
        tile[ty + r][tx] = W[(size_t)(k0 + ty + r) * N + n0 + tx];
    __syncthreads();
    #pragma unroll
    for (int r = 0; r < 32; r += 8)
        Wt[(size_t)(n0 + ty + r) * K + k0 + tx] = tile[tx][ty + r];
}

// ---------------- tf32 tensor-core GEMM ----------------
// C[M,N] = A[M,K] @ Bt[N,K]^T.  128x128 CTA tile, 8 warps (2m x 4n), warp 64x32,
// mma m16n8k8, K-chunk 16, double buffered. Smem pitch 20 words -> conflict-free frags.
// EPI: 0 = +bias; 1 = +bias,GELU; 2 = +bias,+resid
#define GP 20

template<int EPI>
__global__ __launch_bounds__(256) void tfgemm_kernel(
    const float* __restrict__ A, const float* __restrict__ Bt,
    const float* __restrict__ bias, const float* __restrict__ resid,
    float* __restrict__ C, int Nn, int K)
{
    __shared__ __align__(16) float As[2][128*GP];
    __shared__ __align__(16) float Bs[2][128*GP];
    int tid = threadIdx.x, lane = tid & 31, wid = tid >> 5;
    int wm = wid & 1, wn = wid >> 1;
    int bm = blockIdx.y * 128, bn = blockIdx.x * 128;

    float acc[4][4][4];
    #pragma unroll
    for (int i = 0; i < 4; i++)
        #pragma unroll
        for (int j = 0; j < 4; j++)
            #pragma unroll
            for (int k = 0; k < 4; k++) acc[i][j][k] = 0.f;

    int lr[2], lc[2];
    #pragma unroll
    for (int l = 0; l < 2; l++) { int idx = tid + l * 256; lr[l] = idx >> 2; lc[l] = (idx & 3) * 4; }
    float4 ra[2], rb[2];

    // prologue: chunk 0 -> buf 0; chunk 1 -> regs
    #pragma unroll
    for (int l = 0; l < 2; l++) {
        ra[l] = *(const float4*)(A  + (size_t)(bm + lr[l]) * K + lc[l]);
        rb[l] = *(const float4*)(Bt + (size_t)(bn + lr[l]) * K + lc[l]);
    }
    #pragma unroll
    for (int l = 0; l < 2; l++) {
        *(float4*)&As[0][lr[l]*GP + lc[l]] = ra[l];
        *(float4*)&Bs[0][lr[l]*GP + lc[l]] = rb[l];
    }
    if (K > 16) {
        #pragma unroll
        for (int l = 0; l < 2; l++) {
            ra[l] = *(const float4*)(A  + (size_t)(bm + lr[l]) * K + 16 + lc[l]);
            rb[l] = *(const float4*)(Bt + (size_t)(bn + lr[l]) * K + 16 + lc[l]);
        }
    }
    __syncthreads();

    int nst = K / 16, cur = 0;
    for (int t = 0; t < nst; t++) {
        const float* Ac = &As[cur][0];
        const float* Bc = &Bs[cur][0];
        #pragma unroll
        for (int ks = 0; ks < 2; ks++) {
            int k0 = ks * 8 + (lane & 3);
            uint32_t af[4][4], bfr[4][2];
            #pragma unroll
            for (int mf = 0; mf < 4; mf++) {
                int r = wm * 64 + mf * 16 + (lane >> 2);
                af[mf][0] = __float_as_uint(Ac[r*GP + k0]);
                af[mf][1] = __float_as_uint(Ac[(r+8)*GP + k0]);
                af[mf][2] = __float_as_uint(Ac[r*GP + k0 + 4]);
                af[mf][3] = __float_as_uint(Ac[(r+8)*GP + k0 + 4]);
            }
            #pragma unroll
            for (int nf = 0; nf < 4; nf++) {
                int n = wn * 32 + nf * 8 + (lane >> 2);
                bfr[nf][0] = __float_as_uint(Bc[n*GP + k0]);
                bfr[nf][1] = __float_as_uint(Bc[n*GP + k0 + 4]);
            }
            #pragma unroll
            for (int mf = 0; mf < 4; mf++)
                #pragma unroll
                for (int nf = 0; nf < 4; nf++)
                    mma_tf32(acc[mf][nf], af[mf], bfr[nf]);
        }
        if (t + 1 < nst) {
            int nb = 1 ^ cur;
            #pragma unroll
            for (int l = 0; l < 2; l++) {
                *(float4*)&As[nb][lr[l]*GP + lc[l]] = ra[l];
                *(float4*)&Bs[nb][lr[l]*GP + lc[l]] = rb[l];
            }
            if (t + 2 < nst) {
                int k0 = (t + 2) * 16;
                #pragma unroll
                for (int l = 0; l < 2; l++) {
                    ra[l] = *(const float4*)(A  + (size_t)(bm + lr[l]) * K + k0 + lc[l]);
                    rb[l] = *(const float4*)(Bt + (size_t)(bn + lr[l]) * K + k0 + lc[l]);
                }
            }
        }
        __syncthreads();
        cur ^= 1;
    }

    // epilogue: c0,c1 -> (row, 2*(lane&3)); c2,c3 -> row+8
    int mrow = bm + wm * 64 + (lane >> 2);
    int nc0  = bn + wn * 32 + (lane & 3) * 2;
    #pragma unroll
    for (int nf = 0; nf < 4; nf++) {
        int nc = nc0 + nf * 8;
        float b0 = bias[nc], b1 = bias[nc + 1];
        #pragma unroll
        for (int mf = 0; mf < 4; mf++) {
            #pragma unroll
            for (int half = 0; half < 2; half++) {
                int r = mrow + mf * 16 + half * 8;
                float v0 = acc[mf][nf][half*2 + 0] + b0;
                float v1 = acc[mf][nf][half*2 + 1] + b1;
                if (EPI == 1) { v0 = gelu_exact(v0); v1 = gelu_exact(v1); }
                if (EPI == 2) {
                    float2 rr = *(const float2*)(resid + (size_t)r * Nn + nc);
                    v0 += rr.x; v1 += rr.y;
                }
                *(float2*)(C + (size_t)r * Nn + nc) = make_float2(v0, v1);
            }
        }
    }
}

// ---------------- rearrange: effective Q (shift folded), K, V ----------------
__global__ __launch_bounds__(256) void rearrange_kernel()
{
    int flat = blockIdx.x * blockDim.x + threadIdx.x;
    int d4 = flat & 15;
    int n  = (flat >> 4) % NNq;
    int hb = (flat >> 4) / NNq;
    int h = hb & 7, b = hb >> 3;
    int row = b * NNq + n;
    int c4  = (h * 64 + d4 * 4) >> 2;

    const float4* qkv4 = (const float4*)g_qkv;
    float4 q = qkv4[(size_t)row * 384 + c4];
    if (n >= 512) {
        float4 t = qkv4[(size_t)(row - 512) * 384 + c4];
        q.x += 0.5f * t.x; q.y += 0.5f * t.y; q.z += 0.5f * t.z; q.w += 0.5f * t.w;
    }
    if (n >= 1024) {
        float4 t = qkv4[(size_t)(row - 1024) * 384 + c4];
        q.x += 0.25f * t.x; q.y += 0.25f * t.y; q.z += 0.25f * t.z; q.w += 0.25f * t.w;
    }
    q.x *= 0.125f; q.y *= 0.125f; q.z *= 0.125f; q.w *= 0.125f;
    ((float4*)g_qe)[flat] = q;
    ((float4*)g_kt)[flat] = qkv4[(size_t)row * 384 + 128 + c4];
    ((float4*)g_vt)[flat] = qkv4[(size_t)row * 384 + 256 + c4];
}

// ---------------- flash attention: BQ=BK=64, double-buffered, FFMA2 ----------------
__device__ __forceinline__ void attn_ld_tile(
    const float* K, const float* V, int kt, int tid, float4* kreg, float4* vreg)
{
    const float4* Kg = (const float4*)(K + (size_t)kt * 64 * DD);
    const float4* Vg = (const float4*)(V + (size_t)kt * 64 * DD);
    #pragma unroll
    for (int l = 0; l < 4; l++) {
        kreg[l] = Kg[tid + l * 256];
        vreg[l] = Vg[tid + l * 256];
    }
}
__device__ __forceinline__ void attn_st_tile(
    float* KsT, float* Vs, int tid, const float4* kreg, const float4* vreg)
{
    #pragma unroll
    for (int l = 0; l < 4; l++) {
        int idx = tid + l * 256;
        int r = idx >> 4, cg = idx & 15;
        float4 kv = kreg[l];
        KsT[(cg*4+0)*68 + r] = kv.x;
        KsT[(cg*4+1)*68 + r] = kv.y;
        KsT[(cg*4+2)*68 + r] = kv.z;
        KsT[(cg*4+3)*68 + r] = kv.w;
        ((float4*)Vs)[idx] = vreg[l];
    }
}

__global__ __launch_bounds__(256, 2) void attn_kernel(
    const float* __restrict__ x, float* __restrict__ x2)
{
    extern __shared__ __align__(16) float sm[];
    float* Qs  = sm;
    float* Ks0 = sm + 4096;
    float* Ks1 = Ks0 + 4352;
    float* Vs0 = Ks1 + 4352;
    float* Vs1 = Vs0 + 4096;
    float* Ps  = Vs1 + 4096;
    float* KsB[2] = {Ks0, Ks1};
    float* VsB[2] = {Vs0, Vs1};

    int tid = threadIdx.x;
    int tx = tid & 15, ty = tid >> 4;
    int bh = blockIdx.y;
    int q0 = blockIdx.x * 64;
    const float* Q = g_qe + (size_t)bh * NNq * DD + (size_t)q0 * DD;
    const float* K = g_kt + (size_t)bh * NNq * DD;
    const float* V = g_vt + (size_t)bh * NNq * DD;

    float4 kreg[4], vreg[4];
    #pragma unroll
    for (int l = 0; l < 4; l++)
        ((float4*)Qs)[tid + l * 256] = ((const float4*)Q)[tid + l * 256];
    attn_ld_tile(K, V, 0, tid, kreg, vreg);
    attn_st_tile(Ks0, Vs0, tid, kreg, vreg);
    attn_ld_tile(K, V, 1, tid, kreg, vreg);
    __syncthreads();

    float m_run[4], l_run[4];
    u64 oacc[4][2];
    #pragma unroll
    for (int i = 0; i < 4; i++) {
        m_run[i] = -3.0e38f; l_run[i] = 0.f;
        oacc[i][0] = 0ull; oacc[i][1] = 0ull;
    }

    int cur = 0;
    for (int kt = 0; kt < NT; kt++) {
        const float* KsT = KsB[cur];
        const float* Vs  = VsB[cur];

        u64 sP[4][2];
        #pragma unroll
        for (int i = 0; i < 4; i++) { sP[i][0] = 0ull; sP[i][1] = 0ull; }
        #pragma unroll
        for (int d4 = 0; d4 < 16; d4++) {
            float4 qv[4];
            #pragma unroll
            for (int i = 0; i < 4; i++)
                qv[i] = *(const float4*)&Qs[(ty*4 + i) * 64 + d4 * 4];
            #pragma unroll
            for (int dd = 0; dd < 4; dd++) {
                ulonglong2 kb = *(const ulonglong2*)&KsT[(d4*4 + dd) * 68 + tx*4];
                #pragma unroll
                for (int i = 0; i < 4; i++) {
                    float qs = (dd == 0) ? qv[i].x : (dd == 1) ? qv[i].y : (dd == 2) ? qv[i].z : qv[i].w;
                    u64 qp = pk2(qs, qs);
                    sP[i][0] = ffma2(qp, kb.x, sP[i][0]);
                    sP[i][1] = ffma2(qp, kb.y, sP[i][1]);
                }
            }
        }

        #pragma unroll
        for (int i = 0; i < 4; i++) {
            float s0, s1, s2, s3;
            upk2(sP[i][0], s0, s1);
            upk2(sP[i][1], s2, s3);
            float mx = fmaxf(fmaxf(s0, s1), fmaxf(s2, s3));
            #pragma unroll
            for (int m = 1; m < 16; m <<= 1)
                mx = fmaxf(mx, __shfl_xor_sync(0xffffffffu, mx, m));
            float mnew = fmaxf(m_run[i], mx);
            float corr = __expf(m_run[i] - mnew);
            float p0 = __expf(s0 - mnew), p1 = __expf(s1 - mnew);
            float p2 = __expf(s2 - mnew), p3 = __expf(s3 - mnew);
            float sum = p0 + p1 + p2 + p3;
            #pragma unroll
            for (int m = 1; m < 16; m <<= 1)
                sum += __shfl_xor_sync(0xffffffffu, sum, m);
            l_run[i] = l_run[i] * corr + sum;
            m_run[i] = mnew;
            u64 cp = pk2(corr, corr);
            oacc[i][0] = fmul2(oacc[i][0], cp);
            oacc[i][1] = fmul2(oacc[i][1], cp);
            *(float4*)&Ps[(ty*4 + i) * 68 + tx*4] = make_float4(p0, p1, p2, p3);
        }
        __syncthreads();

        #pragma unroll
        for (int k4 = 0; k4 < 16; k4++) {
            float4 pv[4];
            #pragma unroll
            for (int i = 0; i < 4; i++)
                pv[i] = *(const float4*)&Ps[(ty*4 + i) * 68 + k4 * 4];
            #pragma unroll
            for (int kk = 0; kk < 4; kk++) {
                ulonglong2 vv = *(const ulonglong2*)&Vs[(k4*4 + kk) * 64 + tx*4];
                #pragma unroll
                for (int i = 0; i < 4; i++) {
                    float pvs = (kk == 0) ? pv[i].x : (kk == 1) ? pv[i].y : (kk == 2) ? pv[i].z : pv[i].w;
                    u64 pp = pk2(pvs, pvs);
                    oacc[i][0] = ffma2(pp, vv.x, oacc[i][0]);
                    oacc[i][1] = ffma2(pp, vv.y, oacc[i][1]);
                }
            }
        }

        if (kt + 1 < NT) {
            attn_st_tile(KsB[1 ^ cur], VsB[1 ^ cur], tid, kreg, vreg);
            if (kt + 2 < NT)
                attn_ld_tile(K, V, kt + 2, tid, kreg, vreg);
        }
        __syncthreads();
        cur ^= 1;
    }

    int b = bh >> 3, h = bh & 7;
    #pragma unroll
    for (int i = 0; i < 4; i++) {
        float inv = 1.0f / l_run[i];
        float o0, o1, o2, o3;
        upk2(oacc[i][0], o0, o1);
        upk2(oacc[i][1], o2, o3);
        int n = q0 + ty*4 + i;
        size_t off = ((size_t)(b * NNq + n)) * CC + h * 64 + tx * 4;
        float4 xr = *(const float4*)(x + off);
        *(float4*)(x2 + off) = make_float4(
            xr.x + o0 * inv, xr.y + o1 * inv,
            xr.z + o2 * inv, xr.w + o3 * inv);
    }
}

// ---------------- host ----------------
extern "C" void kernel_launch(void* const* d_in, const int* in_sizes, int n_in,
                              void* d_out, int out_size)
{
    const float* x     = (const float*)d_in[0];
    const float* ln1_g = (const float*)d_in[1];
    const float* ln1_b = (const float*)d_in[2];
    const float* qkv_w = (const float*)d_in[3];
    const float* qkv_b = (const float*)d_in[4];
    const float* ln2_g = (const float*)d_in[5];
    const float* ln2_b = (const float*)d_in[6];
    const float* fc1_w = (const float*)d_in[7];
    const float* fc1_b = (const float*)d_in[8];
    const float* fc2_w = (const float*)d_in[9];
    const float* fc2_b = (const float*)d_in[10];
    float* out = (float*)d_out;

    float *p_h, *p_qkv, *p_x2, *p_h2, *p_act, *p_wq, *p_w1, *p_w2;
    cudaGetSymbolAddress((void**)&p_h,   g_h);
    cudaGetSymbolAddress((void**)&p_qkv, g_qkv);
    cudaGetSymbolAddress((void**)&p_x2,  g_x2);
    cudaGetSymbolAddress((void**)&p_h2,  g_h2);
    cudaGetSymbolAddress((void**)&p_act, g_act);
    cudaGetSymbolAddress((void**)&p_wq,  g_wq);
    cudaGetSymbolAddress((void**)&p_w1,  g_w1);
    cudaGetSymbolAddress((void**)&p_w2,  g_w2);

    const int ATTN_SMEM = (4096 + 2*4352 + 2*4096 + 4352) * 4;   // 101376 B
    cudaFuncSetAttribute(attn_kernel, cudaFuncAttributeMaxDynamicSharedMemorySize, ATTN_SMEM);

    // weight transposes -> [N][K] fp32
    transpose_kernel<<<dim3(1536/32, 512/32), 256>>>(qkv_w, p_wq, 512, 1536);
    transpose_kernel<<<dim3(1024/32, 512/32), 256>>>(fc1_w, p_w1, 512, 1024);
    transpose_kernel<<<dim3(512/32, 1024/32), 256>>>(fc2_w, p_w2, 1024, 512);

    // 1. LN1
    ln_kernel<<<ROWS, 128>>>(x, ln1_g, ln1_b, p_h);
    // 2. QKV projection (tf32 tensor cores)
    tfgemm_kernel<0><<<dim3(1536/128, ROWS/128), 256>>>(p_h, p_wq, qkv_b, nullptr, p_qkv, 1536, 512);
    // 3. effective-Q / K / V rearrange
    rearrange_kernel<<<(BB*HH*NNq*DD/4)/256, 256>>>();
    // 4. flash attention + residual into x2
    attn_kernel<<<dim3(NNq/64, BB*HH), 256, ATTN_SMEM>>>(x, p_x2);
    // 5. LN2
    ln_kernel<<<ROWS, 128>>>(p_x2, ln2_g, ln2_b, p_h2);
    // 6. FC1 + GELU (tf32)
    tfgemm_kernel<1><<<dim3(HID/128, ROWS/128), 256>>>(p_h2, p_w1, fc1_b, nullptr, p_act, HID, 512);
    // 7. FC2 + residual (tf32) -> out
    tfgemm_kernel<2><<<dim3(CC/128, ROWS/128), 256>>>(p_act, p_w2, fc2_b, p_x2, out, CC, 1024);
}

// round 12
// speedup vs baseline: 2.0241x; 1.4741x over previous
#include <cuda_runtime.h>
#include <cuda_bf16.h>
#include <math.h>
#include <stdint.h>

#define BB   4
#define NNq  1536
#define CC   512
#define HH   8
#define DD   64
#define HID  1024
#define ROWS (BB*NNq)   // 6144
#define NT   (NNq/64)   // 24 key tiles

// ---------------- scratch (static device globals; no allocation) ----------------
__device__ float g_h  [ROWS*CC];        // ln1 out
__device__ float g_qkv[ROWS*3*CC];
__device__ float g_qe [BB*HH*NNq*DD];
__device__ float g_kt [BB*HH*NNq*DD];
__device__ float g_vt [BB*HH*NNq*DD];
__device__ float g_x2 [ROWS*CC];
__device__ float g_h2 [ROWS*CC];        // ln2 out
__device__ float g_act[ROWS*HID];       // gelu(fc1)
__device__ float g_wq [1536*512];       // qkv_w^T [N][K]
__device__ float g_w1 [1024*512];       // fc1_w^T
__device__ float g_w2 [512*1024];       // fc2_w^T

__device__ __forceinline__ float gelu_exact(float v) {
    return 0.5f * v * (1.0f + erff(v * 0.70710678118654752440f));
}

// tf32 mma (GEMMs)
__device__ __forceinline__ void mma_tf32(float* c, const uint32_t* a, const uint32_t* b) {
    asm volatile("mma.sync.aligned.m16n8k8.row.col.f32.tf32.tf32.f32 "
        "{%0,%1,%2,%3}, {%4,%5,%6,%7}, {%8,%9}, {%0,%1,%2,%3};"
        : "+f"(c[0]), "+f"(c[1]), "+f"(c[2]), "+f"(c[3])
        : "r"(a[0]), "r"(a[1]), "r"(a[2]), "r"(a[3]), "r"(b[0]), "r"(b[1]));
}
// bf16 mma (attention)
__device__ __forceinline__ void mma_bf16(float* c, const uint32_t* a, const uint32_t* b) {
    asm volatile("mma.sync.aligned.m16n8k16.row.col.f32.bf16.bf16.f32 "
        "{%0,%1,%2,%3}, {%4,%5,%6,%7}, {%8,%9}, {%0,%1,%2,%3};"
        : "+f"(c[0]), "+f"(c[1]), "+f"(c[2]), "+f"(c[3])
        : "r"(a[0]), "r"(a[1]), "r"(a[2]), "r"(a[3]), "r"(b[0]), "r"(b[1]));
}

// split fp32 pair -> packed bf16 hi word + lo word (low half = first arg)
__device__ __forceinline__ void split2(float a, float b, uint32_t& hi, uint32_t& lo) {
    __nv_bfloat16 ah = __float2bfloat16(a), bh = __float2bfloat16(b);
    __nv_bfloat16 al = __float2bfloat16(a - __bfloat162float(ah));
    __nv_bfloat16 bl = __float2bfloat16(b - __bfloat162float(bh));
    hi = (uint32_t)__bfloat16_as_ushort(ah) | ((uint32_t)__bfloat16_as_ushort(bh) << 16);
    lo = (uint32_t)__bfloat16_as_ushort(al) | ((uint32_t)__bfloat16_as_ushort(bl) << 16);
}

// FMA-pipe exp (no MUFU): exp(x) for x <= 0, clamped at -87
__device__ __forceinline__ float fexp(float x) {
    float xc = fmaxf(x, -87.0f);
    float y  = xc * 1.4426950408889634f;
    float t  = y + 12582912.0f;                 // round-to-nearest via magic
    float n  = t - 12582912.0f;
    float f  = y - n;
    float p  = 0.0013333558f;
    p = fmaf(p, f, 0.0096181291f);
    p = fmaf(p, f, 0.0555041087f);
    p = fmaf(p, f, 0.2402265069f);
    p = fmaf(p, f, 0.6931471806f);
    p = fmaf(p, f, 1.0f);
    int ni = __float_as_int(t) - 0x4B400000;    // integer n
    float sc = __int_as_float((ni + 127) << 23);
    return sc * p;
}

// ---------------- LayerNorm: one block (128 thr) per row of 512 ----------------
__global__ __launch_bounds__(128) void ln_kernel(
    const float* __restrict__ x, const float* __restrict__ g,
    const float* __restrict__ b, float* __restrict__ out)
{
    int row = blockIdx.x;
    int t = threadIdx.x;
    const float4* xr = (const float4*)(x + (size_t)row * CC);
    float4 v = xr[t];
    float s  = v.x + v.y + v.z + v.w;
    float sq = v.x*v.x + v.y*v.y + v.z*v.z + v.w*v.w;
    #pragma unroll
    for (int o = 16; o; o >>= 1) {
        s  += __shfl_xor_sync(0xffffffffu, s,  o);
        sq += __shfl_xor_sync(0xffffffffu, sq, o);
    }
    __shared__ float rs[4], rq[4];
    int w = t >> 5;
    if ((t & 31) == 0) { rs[w] = s; rq[w] = sq; }
    __syncthreads();
    s  = rs[0] + rs[1] + rs[2] + rs[3];
    sq = rq[0] + rq[1] + rq[2] + rq[3];
    float mean = s * (1.0f / CC);
    float var  = sq * (1.0f / CC) - mean * mean;
    float rstd = rsqrtf(var + 1e-5f);
    float4 gv = ((const float4*)g)[t];
    float4 bv = ((const float4*)b)[t];
    float4 o4;
    o4.x = (v.x - mean) * rstd * gv.x + bv.x;
    o4.y = (v.y - mean) * rstd * gv.y + bv.y;
    o4.z = (v.z - mean) * rstd * gv.z + bv.z;
    o4.w = (v.w - mean) * rstd * gv.w + bv.w;
    ((float4*)(out + (size_t)row * CC))[t] = o4;
}

// ---------------- weight transpose: Wt[n][k] = W[k][n] (fp32) ----------------
__global__ __launch_bounds__(256) void transpose_kernel(
    const float* __restrict__ W, float* __restrict__ Wt, int K, int N)
{
    __shared__ float tile[32][33];
    int n0 = blockIdx.x * 32, k0 = blockIdx.y * 32;
    int tx = threadIdx.x & 31, ty = threadIdx.x >> 5;
    #pragma unroll
    for (int r = 0; r < 32; r += 8)
        tile[ty + r][tx] = W[(size_t)(k0 + ty + r) * N + n0 + tx];
    __syncthreads();
    #pragma unroll
    for (int r = 0; r < 32; r += 8)
        Wt[(size_t)(n0 + ty + r) * K + k0 + tx] = tile[tx][ty + r];
}

// ---------------- tf32 tensor-core GEMM (unchanged from R9) ----------------
#define GP 20
template<int EPI>
__global__ __launch_bounds__(256) void tfgemm_kernel(
    const float* __restrict__ A, const float* __restrict__ Bt,
    const float* __restrict__ bias, const float* __restrict__ resid,
    float* __restrict__ C, int Nn, int K)
{
    __shared__ __align__(16) float As[2][128*GP];
    __shared__ __align__(16) float Bs[2][128*GP];
    int tid = threadIdx.x, lane = tid & 31, wid = tid >> 5;
    int wm = wid & 1, wn = wid >> 1;
    int bm = blockIdx.y * 128, bn = blockIdx.x * 128;

    float acc[4][4][4];
    #pragma unroll
    for (int i = 0; i < 4; i++)
        #pragma unroll
        for (int j = 0; j < 4; j++)
            #pragma unroll
            for (int k = 0; k < 4; k++) acc[i][j][k] = 0.f;

    int lr[2], lc[2];
    #pragma unroll
    for (int l = 0; l < 2; l++) { int idx = tid + l * 256; lr[l] = idx >> 2; lc[l] = (idx & 3) * 4; }
    float4 ra[2], rb[2];

    #pragma unroll
    for (int l = 0; l < 2; l++) {
        ra[l] = *(const float4*)(A  + (size_t)(bm + lr[l]) * K + lc[l]);
        rb[l] = *(const float4*)(Bt + (size_t)(bn + lr[l]) * K + lc[l]);
    }
    #pragma unroll
    for (int l = 0; l < 2; l++) {
        *(float4*)&As[0][lr[l]*GP + lc[l]] = ra[l];
        *(float4*)&Bs[0][lr[l]*GP + lc[l]] = rb[l];
    }
    if (K > 16) {
        #pragma unroll
        for (int l = 0; l < 2; l++) {
            ra[l] = *(const float4*)(A  + (size_t)(bm + lr[l]) * K + 16 + lc[l]);
            rb[l] = *(const float4*)(Bt + (size_t)(bn + lr[l]) * K + 16 + lc[l]);
        }
    }
    __syncthreads();

    int nst = K / 16, cur = 0;
    for (int t = 0; t < nst; t++) {
        const float* Ac = &As[cur][0];
        const float* Bc = &Bs[cur][0];
        #pragma unroll
        for (int ks = 0; ks < 2; ks++) {
            int k0 = ks * 8 + (lane & 3);
            uint32_t af[4][4], bfr[4][2];
            #pragma unroll
            for (int mf = 0; mf < 4; mf++) {
                int r = wm * 64 + mf * 16 + (lane >> 2);
                af[mf][0] = __float_as_uint(Ac[r*GP + k0]);
                af[mf][1] = __float_as_uint(Ac[(r+8)*GP + k0]);
                af[mf][2] = __float_as_uint(Ac[r*GP + k0 + 4]);
                af[mf][3] = __float_as_uint(Ac[(r+8)*GP + k0 + 4]);
            }
            #pragma unroll
            for (int nf = 0; nf < 4; nf++) {
                int n = wn * 32 + nf * 8 + (lane >> 2);
                bfr[nf][0] = __float_as_uint(Bc[n*GP + k0]);
                bfr[nf][1] = __float_as_uint(Bc[n*GP + k0 + 4]);
            }
            #pragma unroll
            for (int mf = 0; mf < 4; mf++)
                #pragma unroll
                for (int nf = 0; nf < 4; nf++)
                    mma_tf32(acc[mf][nf], af[mf], bfr[nf]);
        }
        if (t + 1 < nst) {
            int nb = 1 ^ cur;
            #pragma unroll
            for (int l = 0; l < 2; l++) {
                *(float4*)&As[nb][lr[l]*GP + lc[l]] = ra[l];
                *(float4*)&Bs[nb][lr[l]*GP + lc[l]] = rb[l];
            }
            if (t + 2 < nst) {
                int k0 = (t + 2) * 16;
                #pragma unroll
                for (int l = 0; l < 2; l++) {
                    ra[l] = *(const float4*)(A  + (size_t)(bm + lr[l]) * K + k0 + lc[l]);
                    rb[l] = *(const float4*)(Bt + (size_t)(bn + lr[l]) * K + k0 + lc[l]);
                }
            }
        }
        __syncthreads();
        cur ^= 1;
    }

    int mrow = bm + wm * 64 + (lane >> 2);
    int nc0  = bn + wn * 32 + (lane & 3) * 2;
    #pragma unroll
    for (int nf = 0; nf < 4; nf++) {
        int nc = nc0 + nf * 8;
        float b0 = bias[nc], b1 = bias[nc + 1];
        #pragma unroll
        for (int mf = 0; mf < 4; mf++) {
            #pragma unroll
            for (int half = 0; half < 2; half++) {
                int r = mrow + mf * 16 + half * 8;
                float v0 = acc[mf][nf][half*2 + 0] + b0;
                float v1 = acc[mf][nf][half*2 + 1] + b1;
                if (EPI == 1) { v0 = gelu_exact(v0); v1 = gelu_exact(v1); }
                if (EPI == 2) {
                    float2 rr = *(const float2*)(resid + (size_t)r * Nn + nc);
                    v0 += rr.x; v1 += rr.y;
                }
                *(float2*)(C + (size_t)r * Nn + nc) = make_float2(v0, v1);
            }
        }
    }
}

// ---------------- rearrange: effective Q (shift folded), K, V ----------------
__global__ __launch_bounds__(256) void rearrange_kernel()
{
    int flat = blockIdx.x * blockDim.x + threadIdx.x;
    int d4 = flat & 15;
    int n  = (flat >> 4) % NNq;
    int hb = (flat >> 4) / NNq;
    int h = hb & 7, b = hb >> 3;
    int row = b * NNq + n;
    int c4  = (h * 64 + d4 * 4) >> 2;

    const float4* qkv4 = (const float4*)g_qkv;
    float4 q = qkv4[(size_t)row * 384 + c4];
    if (n >= 512) {
        float4 t = qkv4[(size_t)(row - 512) * 384 + c4];
        q.x += 0.5f * t.x; q.y += 0.5f * t.y; q.z += 0.5f * t.z; q.w += 0.5f * t.w;
    }
    if (n >= 1024) {
        float4 t = qkv4[(size_t)(row - 1024) * 384 + c4];
        q.x += 0.25f * t.x; q.y += 0.25f * t.y; q.z += 0.25f * t.z; q.w += 0.25f * t.w;
    }
    q.x *= 0.125f; q.y *= 0.125f; q.z *= 0.125f; q.w *= 0.125f;
    ((float4*)g_qe)[flat] = q;
    ((float4*)g_kt)[flat] = qkv4[(size_t)row * 384 + 128 + c4];
    ((float4*)g_vt)[flat] = qkv4[(size_t)row * 384 + 256 + c4];
}

// ---------------- flash attention: bf16x3 tensor cores, BQ=128, BK=64 ----------------
// smem word offsets (uint32 words), row pitch 36 words (72 bf16)
#define AQP 36
#define AO_QH 0
#define AO_QL 4608
#define AO_KH0 9216
#define AO_KL0 11520
#define AO_KH1 13824
#define AO_KL1 16128
#define AO_VH0 18432
#define AO_VL0 20736
#define AO_VH1 23040
#define AO_VL1 25344
#define AO_PH  27648
#define AO_PL  32256
#define ATTN_WORDS 36864   // 147456 bytes

__global__ __launch_bounds__(256) void attn_kernel(
    const float* __restrict__ x, float* __restrict__ x2)
{
    extern __shared__ __align__(16) uint32_t smw[];
    int tid = threadIdx.x, lane = tid & 31, wid = tid >> 5;
    int bh = blockIdx.y;
    int q0 = blockIdx.x * 128;
    const float* Qg = g_qe + (size_t)bh * NNq * DD + (size_t)q0 * DD;
    const float* Kg = g_kt + (size_t)bh * NNq * DD;
    const float* Vg = g_vt + (size_t)bh * NNq * DD;

    // ---- Q split copy: thread -> row tid>>1, half tid&1 (32 floats = 16 words) ----
    {
        int row = tid >> 1, half = tid & 1;
        const float4* src = (const float4*)(Qg + (size_t)row * DD + half * 32);
        uint32_t wb = row * AQP + half * 16;
        #pragma unroll
        for (int j = 0; j < 8; j++) {
            float4 v = src[j];
            uint32_t h0, l0, h1, l1;
            split2(v.x, v.y, h0, l0);
            split2(v.z, v.w, h1, l1);
            smw[AO_QH + wb + 2*j]     = h0;
            smw[AO_QH + wb + 2*j + 1] = h1;
            smw[AO_QL + wb + 2*j]     = l0;
            smw[AO_QL + wb + 2*j + 1] = l1;
        }
    }

    // prefetch registers
    float4 kr[4];
    float4 va4[2], vb4[2];
    int kkey = tid >> 2, kq = tid & 3;           // K copy: row kkey, d block kq*16
    int vm = tid & 31, vd0 = (tid >> 5) * 8;     // V copy: key pair (2vm,2vm+1), d block vd0

    // load tile 0
    {
        const float4* ks = (const float4*)(Kg + (size_t)kkey * DD + kq * 16);
        #pragma unroll
        for (int j = 0; j < 4; j++) kr[j] = ks[j];
        va4[0] = *(const float4*)(Vg + (size_t)(2*vm)   * DD + vd0);
        va4[1] = *(const float4*)(Vg + (size_t)(2*vm)   * DD + vd0 + 4);
        vb4[0] = *(const float4*)(Vg + (size_t)(2*vm+1) * DD + vd0);
        vb4[1] = *(const float4*)(Vg + (size_t)(2*vm+1) * DD + vd0 + 4);
    }
    // store tile 0 -> buf 0
    {
        uint32_t wb = kkey * AQP + kq * 8;
        #pragma unroll
        for (int j = 0; j < 4; j++) {
            uint32_t h0, l0, h1, l1;
            split2(kr[j].x, kr[j].y, h0, l0);
            split2(kr[j].z, kr[j].w, h1, l1);
            smw[AO_KH0 + wb + 2*j] = h0; smw[AO_KH0 + wb + 2*j + 1] = h1;
            smw[AO_KL0 + wb + 2*j] = l0; smw[AO_KL0 + wb + 2*j + 1] = l1;
        }
        float va[8] = {va4[0].x, va4[0].y, va4[0].z, va4[0].w, va4[1].x, va4[1].y, va4[1].z, va4[1].w};
        float vb[8] = {vb4[0].x, vb4[0].y, vb4[0].z, vb4[0].w, vb4[1].x, vb4[1].y, vb4[1].z, vb4[1].w};
        #pragma unroll
        for (int j = 0; j < 8; j++) {
            uint32_t hi, lo;
            split2(va[j], vb[j], hi, lo);       // low = key 2vm
            smw[AO_VH0 + (vd0 + j) * AQP + vm] = hi;
            smw[AO_VL0 + (vd0 + j) * AQP + vm] = lo;
        }
    }
    // load tile 1 -> regs
    {
        const float* Kb = Kg + 64 * DD;
        const float* Vb = Vg + 64 * DD;
        const float4* ks = (const float4*)(Kb + (size_t)kkey * DD + kq * 16);
        #pragma unroll
        for (int j = 0; j < 4; j++) kr[j] = ks[j];
        va4[0] = *(const float4*)(Vb + (size_t)(2*vm)   * DD + vd0);
        va4[1] = *(const float4*)(Vb + (size_t)(2*vm)   * DD + vd0 + 4);
        vb4[0] = *(const float4*)(Vb + (size_t)(2*vm+1) * DD + vd0);
        vb4[1] = *(const float4*)(Vb + (size_t)(2*vm+1) * DD + vd0 + 4);
    }
    __syncthreads();

    int rbase = wid * 16;
    int lr4 = lane >> 2, lc4 = lane & 3;
    float m_run[2] = {-3.0e38f, -3.0e38f};
    float l_run[2] = {0.f, 0.f};
    float oac[8][4];
    #pragma unroll
    for (int nf = 0; nf < 8; nf++)
        #pragma unroll
        for (int k = 0; k < 4; k++) oac[nf][k] = 0.f;

    int cur = 0;
    for (int kt = 0; kt < NT; kt++) {
        const uint32_t* KH = smw + (cur ? AO_KH1 : AO_KH0);
        const uint32_t* KL = smw + (cur ? AO_KL1 : AO_KL0);
        const uint32_t* VH = smw + (cur ? AO_VH1 : AO_VH0);
        const uint32_t* VL = smw + (cur ? AO_VL1 : AO_VL0);

        // ---- S = Q'K^T (bf16x3) ----
        float c[8][4];
        #pragma unroll
        for (int nf = 0; nf < 8; nf++)
            #pragma unroll
            for (int k = 0; k < 4; k++) c[nf][k] = 0.f;
        #pragma unroll
        for (int ks = 0; ks < 4; ks++) {
            uint32_t aH[4], aL[4];
            uint32_t aw = (rbase + lr4) * AQP + ks * 8 + lc4;
            aH[0] = smw[AO_QH + aw];            aH[1] = smw[AO_QH + aw + 8*AQP];
            aH[2] = smw[AO_QH + aw + 4];        aH[3] = smw[AO_QH + aw + 8*AQP + 4];
            aL[0] = smw[AO_QL + aw];            aL[1] = smw[AO_QL + aw + 8*AQP];
            aL[2] = smw[AO_QL + aw + 4];        aL[3] = smw[AO_QL + aw + 8*AQP + 4];
            #pragma unroll
            for (int nf = 0; nf < 8; nf++) {
                uint32_t bw = (nf * 8 + lr4) * AQP + ks * 8 + lc4;
                uint32_t bH[2] = {KH[bw], KH[bw + 4]};
                uint32_t bL[2] = {KL[bw], KL[bw + 4]};
                mma_bf16(c[nf], aH, bH);
                mma_bf16(c[nf], aH, bL);
                mma_bf16(c[nf], aL, bH);
            }
        }

        // ---- online softmax per row-half, P -> smem ----
        #pragma unroll
        for (int h = 0; h < 2; h++) {
            int ci = h * 2;
            float mx = -3.0e38f;
            #pragma unroll
            for (int nf = 0; nf < 8; nf++)
                mx = fmaxf(mx, fmaxf(c[nf][ci], c[nf][ci + 1]));
            mx = fmaxf(mx, __shfl_xor_sync(0xffffffffu, mx, 1));
            mx = fmaxf(mx, __shfl_xor_sync(0xffffffffu, mx, 2));
            float mnew = fmaxf(m_run[h], mx);
            float corr = fexp(m_run[h] - mnew);
            float sum = 0.f;
            int r = rbase + lr4 + h * 8;
            #pragma unroll
            for (int nf = 0; nf < 8; nf++) {
                float p0 = fexp(c[nf][ci]     - mnew);
                float p1 = fexp(c[nf][ci + 1] - mnew);
                sum += p0 + p1;
                uint32_t hi, lo;
                split2(p0, p1, hi, lo);
                smw[AO_PH + r * AQP + nf * 4 + lc4] = hi;
                smw[AO_PL + r * AQP + nf * 4 + lc4] = lo;
            }
            sum += __shfl_xor_sync(0xffffffffu, sum, 1);
            sum += __shfl_xor_sync(0xffffffffu, sum, 2);
            l_run[h] = l_run[h] * corr + sum;
            m_run[h] = mnew;
            #pragma unroll
            for (int nf = 0; nf < 8; nf++) {
                oac[nf][ci]     *= corr;
                oac[nf][ci + 1] *= corr;
            }
        }
        __syncwarp();

        // ---- O += P V (bf16x3) ----
        #pragma unroll
        for (int ks = 0; ks < 4; ks++) {
            uint32_t aH[4], aL[4];
            uint32_t aw = (rbase + lr4) * AQP + ks * 8 + lc4;
            aH[0] = smw[AO_PH + aw];            aH[1] = smw[AO_PH + aw + 8*AQP];
            aH[2] = smw[AO_PH + aw + 4];        aH[3] = smw[AO_PH + aw + 8*AQP + 4];
            aL[0] = smw[AO_PL + aw];            aL[1] = smw[AO_PL + aw + 8*AQP];
            aL[2] = smw[AO_PL + aw + 4];        aL[3] = smw[AO_PL + aw + 8*AQP + 4];
            #pragma unroll
            for (int nf = 0; nf < 8; nf++) {
                uint32_t bw = (nf * 8 + lr4) * AQP + ks * 8 + lc4;
                uint32_t bH[2] = {VH[bw], VH[bw + 4]};
                uint32_t bL[2] = {VL[bw], VL[bw + 4]};
                mma_bf16(oac[nf], aH, bH);
                mma_bf16(oac[nf], aH, bL);
                mma_bf16(oac[nf], aL, bH);
            }
        }

        // ---- prefetch pipeline ----
        if (kt + 1 < NT) {
            uint32_t KHn = cur ? AO_KH0 : AO_KH1;
            uint32_t KLn = cur ? AO_KL0 : AO_KL1;
            uint32_t VHn = cur ? AO_VH0 : AO_VH1;
            uint32_t VLn = cur ? AO_VL0 : AO_VL1;
            uint32_t wb = kkey * AQP + kq * 8;
            #pragma unroll
            for (int j = 0; j < 4; j++) {
                uint32_t h0, l0, h1, l1;
                split2(kr[j].x, kr[j].y, h0, l0);
                split2(kr[j].z, kr[j].w, h1, l1);
                smw[KHn + wb + 2*j] = h0; smw[KHn + wb + 2*j + 1] = h1;
                smw[KLn + wb + 2*j] = l0; smw[KLn + wb + 2*j + 1] = l1;
            }
            float va[8] = {va4[0].x, va4[0].y, va4[0].z, va4[0].w, va4[1].x, va4[1].y, va4[1].z, va4[1].w};
            float vb[8] = {vb4[0].x, vb4[0].y, vb4[0].z, vb4[0].w, vb4[1].x, vb4[1].y, vb4[1].z, vb4[1].w};
            #pragma unroll
            for (int j = 0; j < 8; j++) {
                uint32_t hi, lo;
                split2(va[j], vb[j], hi, lo);
                smw[VHn + (vd0 + j) * AQP + vm] = hi;
                smw[VLn + (vd0 + j) * AQP + vm] = lo;
            }
            if (kt + 2 < NT) {
                const float* Kb = Kg + (size_t)(kt + 2) * 64 * DD;
                const float* Vb = Vg + (size_t)(kt + 2) * 64 * DD;
                const float4* ks2 = (const float4*)(Kb + (size_t)kkey * DD + kq * 16);
                #pragma unroll
                for (int j = 0; j < 4; j++) kr[j] = ks2[j];
                va4[0] = *(const float4*)(Vb + (size_t)(2*vm)   * DD + vd0);
                va4[1] = *(const float4*)(Vb + (size_t)(2*vm)   * DD + vd0 + 4);
                vb4[0] = *(const float4*)(Vb + (size_t)(2*vm+1) * DD + vd0);
                vb4[1] = *(const float4*)(Vb + (size_t)(2*vm+1) * DD + vd0 + 4);
            }
        }
        __syncthreads();
        cur ^= 1;
    }

    // ---- epilogue: x2 = x + O / l ----
    int b = bh >> 3, hd = bh & 7;
    #pragma unroll
    for (int h = 0; h < 2; h++) {
        float inv = 1.0f / l_run[h];
        int n = q0 + rbase + lr4 + h * 8;
        #pragma unroll
        for (int nf = 0; nf < 8; nf++) {
            int d = nf * 8 + lc4 * 2;
            size_t off = ((size_t)(b * NNq + n)) * CC + hd * 64 + d;
            float2 xr = *(const float2*)(x + off);
            *(float2*)(x2 + off) = make_float2(
                xr.x + oac[nf][h*2]     * inv,
                xr.y + oac[nf][h*2 + 1] * inv);
        }
    }
}

// ---------------- host ----------------
extern "C" void kernel_launch(void* const* d_in, const int* in_sizes, int n_in,
                              void* d_out, int out_size)
{
    const float* x     = (const float*)d_in[0];
    const float* ln1_g = (const float*)d_in[1];
    const float* ln1_b = (const float*)d_in[2];
    const float* qkv_w = (const float*)d_in[3];
    const float* qkv_b = (const float*)d_in[4];
    const float* ln2_g = (const float*)d_in[5];
    const float* ln2_b = (const float*)d_in[6];
    const float* fc1_w = (const float*)d_in[7];
    const float* fc1_b = (const float*)d_in[8];
    const float* fc2_w = (const float*)d_in[9];
    const float* fc2_b = (const float*)d_in[10];
    float* out = (float*)d_out;

    float *p_h, *p_qkv, *p_x2, *p_h2, *p_act, *p_wq, *p_w1, *p_w2;
    cudaGetSymbolAddress((void**)&p_h,   g_h);
    cudaGetSymbolAddress((void**)&p_qkv, g_qkv);
    cudaGetSymbolAddress((void**)&p_x2,  g_x2);
    cudaGetSymbolAddress((void**)&p_h2,  g_h2);
    cudaGetSymbolAddress((void**)&p_act, g_act);
    cudaGetSymbolAddress((void**)&p_wq,  g_wq);
    cudaGetSymbolAddress((void**)&p_w1,  g_w1);
    cudaGetSymbolAddress((void**)&p_w2,  g_w2);

    const int ATTN_SMEM = ATTN_WORDS * 4;   // 147456 B
    cudaFuncSetAttribute(attn_kernel, cudaFuncAttributeMaxDynamicSharedMemorySize, ATTN_SMEM);

    // weight transposes -> [N][K] fp32
    transpose_kernel<<<dim3(1536/32, 512/32), 256>>>(qkv_w, p_wq, 512, 1536);
    transpose_kernel<<<dim3(1024/32, 512/32), 256>>>(fc1_w, p_w1, 512, 1024);
    transpose_kernel<<<dim3(512/32, 1024/32), 256>>>(fc2_w, p_w2, 1024, 512);

    // 1. LN1
    ln_kernel<<<ROWS, 128>>>(x, ln1_g, ln1_b, p_h);
    // 2. QKV projection (tf32 tensor cores)
    tfgemm_kernel<0><<<dim3(1536/128, ROWS/128), 256>>>(p_h, p_wq, qkv_b, nullptr, p_qkv, 1536, 512);
    // 3. effective-Q / K / V rearrange
    rearrange_kernel<<<(BB*HH*NNq*DD/4)/256, 256>>>();
    // 4. flash attention (bf16x3 tensor cores) + residual into x2
    attn_kernel<<<dim3(NNq/128, BB*HH), 256, ATTN_SMEM>>>(x, p_x2);
    // 5. LN2
    ln_kernel<<<ROWS, 128>>>(p_x2, ln2_g, ln2_b, p_h2);
    // 6. FC1 + GELU (tf32)
    tfgemm_kernel<1><<<dim3(HID/128, ROWS/128), 256>>>(p_h2, p_w1, fc1_b, nullptr, p_act, HID, 512);
    // 7. FC2 + residual (tf32) -> out
    tfgemm_kernel<2><<<dim3(CC/128, ROWS/128), 256>>>(p_act, p_w2, fc2_b, p_x2, out, CC, 1024);
}

// round 14
// speedup vs baseline: 2.2786x; 1.1257x over previous
#include <cuda_runtime.h>
#include <cuda_bf16.h>
#include <math.h>
#include <stdint.h>

#define BB   4
#define NNq  1536
#define CC   512
#define HH   8
#define DD   64
#define HID  1024
#define ROWS (BB*NNq)   // 6144
#define NT   (NNq/64)   // 24 key tiles

// ---------------- scratch (static device globals; no allocation) ----------------
__device__ float g_h  [ROWS*CC];        // ln1 out
__device__ float g_qkv[ROWS*3*CC];
__device__ float g_qe [BB*HH*NNq*DD];
__device__ float g_kt [BB*HH*NNq*DD];
__device__ float g_vt [BB*HH*NNq*DD];
__device__ float g_x2 [ROWS*CC];
__device__ float g_h2 [ROWS*CC];        // ln2 out
__device__ float g_act[ROWS*HID];       // gelu(fc1)
__device__ float g_wq [1536*512];       // qkv_w^T [N][K]
__device__ float g_w1 [1024*512];       // fc1_w^T
__device__ float g_w2 [512*1024];       // fc2_w^T

__device__ __forceinline__ float gelu_exact(float v) {
    return 0.5f * v * (1.0f + erff(v * 0.70710678118654752440f));
}

// tf32 mma (GEMMs)
__device__ __forceinline__ void mma_tf32(float* c, const uint32_t* a, const uint32_t* b) {
    asm volatile("mma.sync.aligned.m16n8k8.row.col.f32.tf32.tf32.f32 "
        "{%0,%1,%2,%3}, {%4,%5,%6,%7}, {%8,%9}, {%0,%1,%2,%3};"
        : "+f"(c[0]), "+f"(c[1]), "+f"(c[2]), "+f"(c[3])
        : "r"(a[0]), "r"(a[1]), "r"(a[2]), "r"(a[3]), "r"(b[0]), "r"(b[1]));
}
// bf16 mma (attention)
__device__ __forceinline__ void mma_bf16(float* c, const uint32_t* a, const uint32_t* b) {
    asm volatile("mma.sync.aligned.m16n8k16.row.col.f32.bf16.bf16.f32 "
        "{%0,%1,%2,%3}, {%4,%5,%6,%7}, {%8,%9}, {%0,%1,%2,%3};"
        : "+f"(c[0]), "+f"(c[1]), "+f"(c[2]), "+f"(c[3])
        : "r"(a[0]), "r"(a[1]), "r"(a[2]), "r"(a[3]), "r"(b[0]), "r"(b[1]));
}

// split fp32 pair -> packed bf16 hi word + lo word (low half = first arg)
__device__ __forceinline__ void split2(float a, float b, uint32_t& hi, uint32_t& lo) {
    __nv_bfloat16 ah = __float2bfloat16(a), bh = __float2bfloat16(b);
    __nv_bfloat16 al = __float2bfloat16(a - __bfloat162float(ah));
    __nv_bfloat16 bl = __float2bfloat16(b - __bfloat162float(bh));
    hi = (uint32_t)__bfloat16_as_ushort(ah) | ((uint32_t)__bfloat16_as_ushort(bh) << 16);
    lo = (uint32_t)__bfloat16_as_ushort(al) | ((uint32_t)__bfloat16_as_ushort(bl) << 16);
}

// FMA-pipe exp (no MUFU): exp(x) for x <= 0, clamped at -87
__device__ __forceinline__ float fexp(float x) {
    float xc = fmaxf(x, -87.0f);
    float y  = xc * 1.4426950408889634f;
    float t  = y + 12582912.0f;                 // round-to-nearest via magic
    float n  = t - 12582912.0f;
    float f  = y - n;
    float p  = 0.0013333558f;
    p = fmaf(p, f, 0.0096181291f);
    p = fmaf(p, f, 0.0555041087f);
    p = fmaf(p, f, 0.2402265069f);
    p = fmaf(p, f, 0.6931471806f);
    p = fmaf(p, f, 1.0f);
    int ni = __float_as_int(t) - 0x4B400000;    // integer n
    float sc = __int_as_float((ni + 127) << 23);
    return sc * p;
}

// ---------------- LayerNorm: one block (128 thr) per row of 512 ----------------
__global__ __launch_bounds__(128) void ln_kernel(
    const float* __restrict__ x, const float* __restrict__ g,
    const float* __restrict__ b, float* __restrict__ out)
{
    int row = blockIdx.x;
    int t = threadIdx.x;
    const float4* xr = (const float4*)(x + (size_t)row * CC);
    float4 v = xr[t];
    float s  = v.x + v.y + v.z + v.w;
    float sq = v.x*v.x + v.y*v.y + v.z*v.z + v.w*v.w;
    #pragma unroll
    for (int o = 16; o; o >>= 1) {
        s  += __shfl_xor_sync(0xffffffffu, s,  o);
        sq += __shfl_xor_sync(0xffffffffu, sq, o);
    }
    __shared__ float rs[4], rq[4];
    int w = t >> 5;
    if ((t & 31) == 0) { rs[w] = s; rq[w] = sq; }
    __syncthreads();
    s  = rs[0] + rs[1] + rs[2] + rs[3];
    sq = rq[0] + rq[1] + rq[2] + rq[3];
    float mean = s * (1.0f / CC);
    float var  = sq * (1.0f / CC) - mean * mean;
    float rstd = rsqrtf(var + 1e-5f);
    float4 gv = ((const float4*)g)[t];
    float4 bv = ((const float4*)b)[t];
    float4 o4;
    o4.x = (v.x - mean) * rstd * gv.x + bv.x;
    o4.y = (v.y - mean) * rstd * gv.y + bv.y;
    o4.z = (v.z - mean) * rstd * gv.z + bv.z;
    o4.w = (v.w - mean) * rstd * gv.w + bv.w;
    ((float4*)(out + (size_t)row * CC))[t] = o4;
}

// ---------------- weight transpose: Wt[n][k] = W[k][n] (fp32) ----------------
__global__ __launch_bounds__(256) void transpose_kernel(
    const float* __restrict__ W, float* __restrict__ Wt, int K, int N)
{
    __shared__ float tile[32][33];
    int n0 = blockIdx.x * 32, k0 = blockIdx.y * 32;
    int tx = threadIdx.x & 31, ty = threadIdx.x >> 5;
    #pragma unroll
    for (int r = 0; r < 32; r += 8)
        tile[ty + r][tx] = W[(size_t)(k0 + ty + r) * N + n0 + tx];
    __syncthreads();
    #pragma unroll
    for (int r = 0; r < 32; r += 8)
        Wt[(size_t)(n0 + ty + r) * K + k0 + tx] = tile[tx][ty + r];
}

// ---------------- tf32 tensor-core GEMM (unchanged) ----------------
#define GP 20
template<int EPI>
__global__ __launch_bounds__(256) void tfgemm_kernel(
    const float* __restrict__ A, const float* __restrict__ Bt,
    const float* __restrict__ bias, const float* __restrict__ resid,
    float* __restrict__ C, int Nn, int K)
{
    __shared__ __align__(16) float As[2][128*GP];
    __shared__ __align__(16) float Bs[2][128*GP];
    int tid = threadIdx.x, lane = tid & 31, wid = tid >> 5;
    int wm = wid & 1, wn = wid >> 1;
    int bm = blockIdx.y * 128, bn = blockIdx.x * 128;

    float acc[4][4][4];
    #pragma unroll
    for (int i = 0; i < 4; i++)
        #pragma unroll
        for (int j = 0; j < 4; j++)
            #pragma unroll
            for (int k = 0; k < 4; k++) acc[i][j][k] = 0.f;

    int lr[2], lc[2];
    #pragma unroll
    for (int l = 0; l < 2; l++) { int idx = tid + l * 256; lr[l] = idx >> 2; lc[l] = (idx & 3) * 4; }
    float4 ra[2], rb[2];

    #pragma unroll
    for (int l = 0; l < 2; l++) {
        ra[l] = *(const float4*)(A  + (size_t)(bm + lr[l]) * K + lc[l]);
        rb[l] = *(const float4*)(Bt + (size_t)(bn + lr[l]) * K + lc[l]);
    }
    #pragma unroll
    for (int l = 0; l < 2; l++) {
        *(float4*)&As[0][lr[l]*GP + lc[l]] = ra[l];
        *(float4*)&Bs[0][lr[l]*GP + lc[l]] = rb[l];
    }
    if (K > 16) {
        #pragma unroll
        for (int l = 0; l < 2; l++) {
            ra[l] = *(const float4*)(A  + (size_t)(bm + lr[l]) * K + 16 + lc[l]);
            rb[l] = *(const float4*)(Bt + (size_t)(bn + lr[l]) * K + 16 + lc[l]);
        }
    }
    __syncthreads();

    int nst = K / 16, cur = 0;
    for (int t = 0; t < nst; t++) {
        const float* Ac = &As[cur][0];
        const float* Bc = &Bs[cur][0];
        #pragma unroll
        for (int ks = 0; ks < 2; ks++) {
            int k0 = ks * 8 + (lane & 3);
            uint32_t af[4][4], bfr[4][2];
            #pragma unroll
            for (int mf = 0; mf < 4; mf++) {
                int r = wm * 64 + mf * 16 + (lane >> 2);
                af[mf][0] = __float_as_uint(Ac[r*GP + k0]);
                af[mf][1] = __float_as_uint(Ac[(r+8)*GP + k0]);
                af[mf][2] = __float_as_uint(Ac[r*GP + k0 + 4]);
                af[mf][3] = __float_as_uint(Ac[(r+8)*GP + k0 + 4]);
            }
            #pragma unroll
            for (int nf = 0; nf < 4; nf++) {
                int n = wn * 32 + nf * 8 + (lane >> 2);
                bfr[nf][0] = __float_as_uint(Bc[n*GP + k0]);
                bfr[nf][1] = __float_as_uint(Bc[n*GP + k0 + 4]);
            }
            #pragma unroll
            for (int mf = 0; mf < 4; mf++)
                #pragma unroll
                for (int nf = 0; nf < 4; nf++)
                    mma_tf32(acc[mf][nf], af[mf], bfr[nf]);
        }
        if (t + 1 < nst) {
            int nb = 1 ^ cur;
            #pragma unroll
            for (int l = 0; l < 2; l++) {
                *(float4*)&As[nb][lr[l]*GP + lc[l]] = ra[l];
                *(float4*)&Bs[nb][lr[l]*GP + lc[l]] = rb[l];
            }
            if (t + 2 < nst) {
                int k0 = (t + 2) * 16;
                #pragma unroll
                for (int l = 0; l < 2; l++) {
                    ra[l] = *(const float4*)(A  + (size_t)(bm + lr[l]) * K + k0 + lc[l]);
                    rb[l] = *(const float4*)(Bt + (size_t)(bn + lr[l]) * K + k0 + lc[l]);
                }
            }
        }
        __syncthreads();
        cur ^= 1;
    }

    int mrow = bm + wm * 64 + (lane >> 2);
    int nc0  = bn + wn * 32 + (lane & 3) * 2;
    #pragma unroll
    for (int nf = 0; nf < 4; nf++) {
        int nc = nc0 + nf * 8;
        float b0 = bias[nc], b1 = bias[nc + 1];
        #pragma unroll
        for (int mf = 0; mf < 4; mf++) {
            #pragma unroll
            for (int half = 0; half < 2; half++) {
                int r = mrow + mf * 16 + half * 8;
                float v0 = acc[mf][nf][half*2 + 0] + b0;
                float v1 = acc[mf][nf][half*2 + 1] + b1;
                if (EPI == 1) { v0 = gelu_exact(v0); v1 = gelu_exact(v1); }
                if (EPI == 2) {
                    float2 rr = *(const float2*)(resid + (size_t)r * Nn + nc);
                    v0 += rr.x; v1 += rr.y;
                }
                *(float2*)(C + (size_t)r * Nn + nc) = make_float2(v0, v1);
            }
        }
    }
}

// ---------------- rearrange: effective Q (shift folded), K, V ----------------
__global__ __launch_bounds__(256) void rearrange_kernel()
{
    int flat = blockIdx.x * blockDim.x + threadIdx.x;
    int d4 = flat & 15;
    int n  = (flat >> 4) % NNq;
    int hb = (flat >> 4) / NNq;
    int h = hb & 7, b = hb >> 3;
    int row = b * NNq + n;
    int c4  = (h * 64 + d4 * 4) >> 2;

    const float4* qkv4 = (const float4*)g_qkv;
    float4 q = qkv4[(size_t)row * 384 + c4];
    if (n >= 512) {
        float4 t = qkv4[(size_t)(row - 512) * 384 + c4];
        q.x += 0.5f * t.x; q.y += 0.5f * t.y; q.z += 0.5f * t.z; q.w += 0.5f * t.w;
    }
    if (n >= 1024) {
        float4 t = qkv4[(size_t)(row - 1024) * 384 + c4];
        q.x += 0.25f * t.x; q.y += 0.25f * t.y; q.z += 0.25f * t.z; q.w += 0.25f * t.w;
    }
    q.x *= 0.125f; q.y *= 0.125f; q.z *= 0.125f; q.w *= 0.125f;
    ((float4*)g_qe)[flat] = q;
    ((float4*)g_kt)[flat] = qkv4[(size_t)row * 384 + 128 + c4];
    ((float4*)g_vt)[flat] = qkv4[(size_t)row * 384 + 256 + c4];
}

// ---------------- flash attention: bf16x3 MMA, reg-Q, reg-P, 2 CTA/SM ----------------
// smem (single buffer, word offsets, pitch 36 words = 72 bf16):
//   KH 0, KL 2304, VH 4608, VL 6912; total 9216 words = 36864 B
#define AQP 36
#define ATTN_WORDS 9216

__global__ __launch_bounds__(256, 2) void attn_kernel(
    const float* __restrict__ x, float* __restrict__ x2)
{
    extern __shared__ __align__(16) uint32_t smw[];
    uint32_t* KH = smw;
    uint32_t* KL = smw + 2304;
    uint32_t* VH = smw + 4608;
    uint32_t* VL = smw + 6912;

    int tid = threadIdx.x, lane = tid & 31, wid = tid >> 5;
    int bh = blockIdx.y;
    int q0 = blockIdx.x * 128;
    const float* Qg = g_qe + (size_t)bh * NNq * DD + (size_t)q0 * DD;
    const float* Kg = g_kt + (size_t)bh * NNq * DD;
    const float* Vg = g_vt + (size_t)bh * NNq * DD;

    int rbase = wid * 16;
    int lr4 = lane >> 2, lc4 = lane & 3;

    // ---- Q fragments: loaded from gmem ONCE, live in registers all 24 tiles ----
    uint32_t qH[4][4], qL[4][4];
    {
        const float* Qr0 = Qg + (size_t)(rbase + lr4) * DD;
        const float* Qr1 = Qr0 + 8 * DD;
        #pragma unroll
        for (int ks = 0; ks < 4; ks++) {
            int d0 = ks * 16 + 2 * lc4;
            float2 a = *(const float2*)(Qr0 + d0);
            float2 b = *(const float2*)(Qr1 + d0);
            float2 c = *(const float2*)(Qr0 + d0 + 8);
            float2 d = *(const float2*)(Qr1 + d0 + 8);
            split2(a.x, a.y, qH[ks][0], qL[ks][0]);
            split2(b.x, b.y, qH[ks][1], qL[ks][1]);
            split2(c.x, c.y, qH[ks][2], qL[ks][2]);
            split2(d.x, d.y, qH[ks][3], qL[ks][3]);
        }
    }

    float m_run[2] = {-3.0e38f, -3.0e38f};
    float l_run[2] = {0.f, 0.f};
    float oac[8][4];
    #pragma unroll
    for (int nf = 0; nf < 8; nf++)
        #pragma unroll
        for (int k = 0; k < 4; k++) oac[nf][k] = 0.f;

    int kkey = tid >> 2, kq = tid & 3;        // K loader: row kkey, d block kq*16
    int vm = tid & 31, vd0 = (tid >> 5) * 8;  // V loader: key pair (2vm,2vm+1), d rows vd0..+7

    for (int kt = 0; kt < NT; kt++) {
        __syncthreads();   // all reads of previous tile done
        // ---- load K/V tile kt -> smem (split bf16 hi/lo) ----
        {
            const float* Kb = Kg + (size_t)kt * 64 * DD;
            const float* Vb = Vg + (size_t)kt * 64 * DD;
            const float4* ks4 = (const float4*)(Kb + (size_t)kkey * DD + kq * 16);
            uint32_t wb = kkey * AQP + kq * 8;
            #pragma unroll
            for (int j = 0; j < 4; j++) {
                float4 v = ks4[j];
                uint32_t h0, l0, h1, l1;
                split2(v.x, v.y, h0, l0);
                split2(v.z, v.w, h1, l1);
                KH[wb + 2*j] = h0; KH[wb + 2*j + 1] = h1;
                KL[wb + 2*j] = l0; KL[wb + 2*j + 1] = l1;
            }
            float4 va4[2], vb4[2];
            va4[0] = *(const float4*)(Vb + (size_t)(2*vm)   * DD + vd0);
            va4[1] = *(const float4*)(Vb + (size_t)(2*vm)   * DD + vd0 + 4);
            vb4[0] = *(const float4*)(Vb + (size_t)(2*vm+1) * DD + vd0);
            vb4[1] = *(const float4*)(Vb + (size_t)(2*vm+1) * DD + vd0 + 4);
            float va[8] = {va4[0].x, va4[0].y, va4[0].z, va4[0].w, va4[1].x, va4[1].y, va4[1].z, va4[1].w};
            float vb[8] = {vb4[0].x, vb4[0].y, vb4[0].z, vb4[0].w, vb4[1].x, vb4[1].y, vb4[1].z, vb4[1].w};
            #pragma unroll
            for (int j = 0; j < 8; j++) {
                uint32_t hi, lo;
                split2(va[j], vb[j], hi, lo);     // low half = key 2vm
                VH[(vd0 + j) * AQP + vm] = hi;
                VL[(vd0 + j) * AQP + vm] = lo;
            }
        }
        __syncthreads();

        // ---- S = Q'K^T (bf16x3), Q frags from registers ----
        float c[8][4];
        #pragma unroll
        for (int nf = 0; nf < 8; nf++)
            #pragma unroll
            for (int k = 0; k < 4; k++) c[nf][k] = 0.f;
        #pragma unroll
        for (int ks = 0; ks < 4; ks++) {
            #pragma unroll
            for (int nf = 0; nf < 8; nf++) {
                uint32_t bw = (nf * 8 + lr4) * AQP + ks * 8 + lc4;
                uint32_t bH[2] = {KH[bw], KH[bw + 4]};
                uint32_t bL[2] = {KL[bw], KL[bw + 4]};
                mma_bf16(c[nf], qH[ks], bH);
                mma_bf16(c[nf], qH[ks], bL);
                mma_bf16(c[nf], qL[ks], bH);
            }
        }

        // ---- online softmax per row-half, exp in place (P stays in c) ----
        #pragma unroll
        for (int h = 0; h < 2; h++) {
            int ci = h * 2;
            float mx = -3.0e38f;
            #pragma unroll
            for (int nf = 0; nf < 8; nf++)
                mx = fmaxf(mx, fmaxf(c[nf][ci], c[nf][ci + 1]));
            mx = fmaxf(mx, __shfl_xor_sync(0xffffffffu, mx, 1));
            mx = fmaxf(mx, __shfl_xor_sync(0xffffffffu, mx, 2));
            float mnew = fmaxf(m_run[h], mx);
            float corr = fexp(m_run[h] - mnew);
            float sum = 0.f;
            #pragma unroll
            for (int nf = 0; nf < 8; nf++) {
                float p0 = fexp(c[nf][ci]     - mnew);
                float p1 = fexp(c[nf][ci + 1] - mnew);
                c[nf][ci] = p0; c[nf][ci + 1] = p1;
                sum += p0 + p1;
            }
            sum += __shfl_xor_sync(0xffffffffu, sum, 1);
            sum += __shfl_xor_sync(0xffffffffu, sum, 2);
            l_run[h] = l_run[h] * corr + sum;
            m_run[h] = mnew;
            #pragma unroll
            for (int nf = 0; nf < 8; nf++) {
                oac[nf][ci]     *= corr;
                oac[nf][ci + 1] *= corr;
            }
        }

        // ---- O += P V (bf16x3): A-fragments built from c registers (no smem P) ----
        #pragma unroll
        for (int j = 0; j < 4; j++) {        // key chunk 16j
            uint32_t aH[4], aL[4];
            split2(c[2*j][0],     c[2*j][1],     aH[0], aL[0]);   // row lr4,   keys 16j+2lc4..+1
            split2(c[2*j][2],     c[2*j][3],     aH[1], aL[1]);   // row lr4+8
            split2(c[2*j + 1][0], c[2*j + 1][1], aH[2], aL[2]);   // row lr4,   keys 16j+8+2lc4
            split2(c[2*j + 1][2], c[2*j + 1][3], aH[3], aL[3]);   // row lr4+8
            #pragma unroll
            for (int nf = 0; nf < 8; nf++) { // d block
                uint32_t bw = (nf * 8 + lr4) * AQP + j * 8 + lc4;
                uint32_t bH[2] = {VH[bw], VH[bw + 4]};
                uint32_t bL[2] = {VL[bw], VL[bw + 4]};
                mma_bf16(oac[nf], aH, bH);
                mma_bf16(oac[nf], aH, bL);
                mma_bf16(oac[nf], aL, bH);
            }
        }
    }

    // ---- epilogue: x2 = x + O / l ----
    int b = bh >> 3, hd = bh & 7;
    #pragma unroll
    for (int h = 0; h < 2; h++) {
        float inv = 1.0f / l_run[h];
        int n = q0 + rbase + lr4 + h * 8;
        #pragma unroll
        for (int nf = 0; nf < 8; nf++) {
            int d = nf * 8 + lc4 * 2;
            size_t off = ((size_t)(b * NNq + n)) * CC + hd * 64 + d;
            float2 xr = *(const float2*)(x + off);
            *(float2*)(x2 + off) = make_float2(
                xr.x + oac[nf][h*2]     * inv,
                xr.y + oac[nf][h*2 + 1] * inv);
        }
    }
}

// ---------------- host ----------------
extern "C" void kernel_launch(void* const* d_in, const int* in_sizes, int n_in,
                              void* d_out, int out_size)
{
    const float* x     = (const float*)d_in[0];
    const float* ln1_g = (const float*)d_in[1];
    const float* ln1_b = (const float*)d_in[2];
    const float* qkv_w = (const float*)d_in[3];
    const float* qkv_b = (const float*)d_in[4];
    const float* ln2_g = (const float*)d_in[5];
    const float* ln2_b = (const float*)d_in[6];
    const float* fc1_w = (const float*)d_in[7];
    const float* fc1_b = (const float*)d_in[8];
    const float* fc2_w = (const float*)d_in[9];
    const float* fc2_b = (const float*)d_in[10];
    float* out = (float*)d_out;

    float *p_h, *p_qkv, *p_x2, *p_h2, *p_act, *p_wq, *p_w1, *p_w2;
    cudaGetSymbolAddress((void**)&p_h,   g_h);
    cudaGetSymbolAddress((void**)&p_qkv, g_qkv);
    cudaGetSymbolAddress((void**)&p_x2,  g_x2);
    cudaGetSymbolAddress((void**)&p_h2,  g_h2);
    cudaGetSymbolAddress((void**)&p_act, g_act);
    cudaGetSymbolAddress((void**)&p_wq,  g_wq);
    cudaGetSymbolAddress((void**)&p_w1,  g_w1);
    cudaGetSymbolAddress((void**)&p_w2,  g_w2);

    const int ATTN_SMEM = ATTN_WORDS * 4;   // 36864 B -> 2 CTAs/SM
    cudaFuncSetAttribute(attn_kernel, cudaFuncAttributeMaxDynamicSharedMemorySize, ATTN_SMEM);

    // weight transposes -> [N][K] fp32
    transpose_kernel<<<dim3(1536/32, 512/32), 256>>>(qkv_w, p_wq, 512, 1536);
    transpose_kernel<<<dim3(1024/32, 512/32), 256>>>(fc1_w, p_w1, 512, 1024);
    transpose_kernel<<<dim3(512/32, 1024/32), 256>>>(fc2_w, p_w2, 1024, 512);

    // 1. LN1
    ln_kernel<<<ROWS, 128>>>(x, ln1_g, ln1_b, p_h);
    // 2. QKV projection (tf32 tensor cores)
    tfgemm_kernel<0><<<dim3(1536/128, ROWS/128), 256>>>(p_h, p_wq, qkv_b, nullptr, p_qkv, 1536, 512);
    // 3. effective-Q / K / V rearrange
    rearrange_kernel<<<(BB*HH*NNq*DD/4)/256, 256>>>();
    // 4. flash attention (bf16x3, reg-P) + residual into x2
    attn_kernel<<<dim3(NNq/128, BB*HH), 256, ATTN_SMEM>>>(x, p_x2);
    // 5. LN2
    ln_kernel<<<ROWS, 128>>>(p_x2, ln2_g, ln2_b, p_h2);
    // 6. FC1 + GELU (tf32)
    tfgemm_kernel<1><<<dim3(HID/128, ROWS/128), 256>>>(p_h2, p_w1, fc1_b, nullptr, p_act, HID, 512);
    // 7. FC2 + residual (tf32) -> out
    tfgemm_kernel<2><<<dim3(CC/128, ROWS/128), 256>>>(p_act, p_w2, fc2_b, p_x2, out, CC, 1024);
}

// round 17
// speedup vs baseline: 2.5174x; 1.1048x over previous
#include <cuda_runtime.h>
#include <cuda_bf16.h>
#include <math.h>
#include <stdint.h>

#define BB   4
#define NNq  1536
#define CC   512
#define HH   8
#define DD   64
#define HID  1024
#define ROWS (BB*NNq)   // 6144
#define NT   (NNq/64)   // 24 key tiles

// ---------------- scratch (static device globals; no allocation) ----------------
__device__ float g_h  [ROWS*CC];        // ln1 out
__device__ float g_qkv[ROWS*3*CC];
__device__ float g_qe [BB*HH*NNq*DD];   // effective Q (fp32)
__device__ float g_x2 [ROWS*CC];
__device__ float g_h2 [ROWS*CC];        // ln2 out
__device__ float g_act[ROWS*HID];       // gelu(fc1)
__device__ float g_wq [1536*512];       // qkv_w^T [N][K]
__device__ float g_w1 [1024*512];       // fc1_w^T
__device__ float g_w2 [512*1024];       // fc2_w^T
// pre-split bf16 hi/lo K and V (packed 2 per word)
__device__ uint32_t g_kh[32*1536*32];   // [bh][key][dpair]   hi
__device__ uint32_t g_kl[32*1536*32];   //                    lo
__device__ uint32_t g_vh[32*24*64*32];  // [bh][ktile][d][keypair] hi
__device__ uint32_t g_vl[32*24*64*32];  //                         lo

__device__ __forceinline__ float gelu_exact(float v) {
    return 0.5f * v * (1.0f + erff(v * 0.70710678118654752440f));
}

// tf32 mma (GEMMs)
__device__ __forceinline__ void mma_tf32(float* c, const uint32_t* a, const uint32_t* b) {
    asm volatile("mma.sync.aligned.m16n8k8.row.col.f32.tf32.tf32.f32 "
        "{%0,%1,%2,%3}, {%4,%5,%6,%7}, {%8,%9}, {%0,%1,%2,%3};"
        : "+f"(c[0]), "+f"(c[1]), "+f"(c[2]), "+f"(c[3])
        : "r"(a[0]), "r"(a[1]), "r"(a[2]), "r"(a[3]), "r"(b[0]), "r"(b[1]));
}
// bf16 mma (attention)
__device__ __forceinline__ void mma_bf16(float* c, const uint32_t* a, const uint32_t* b) {
    asm volatile("mma.sync.aligned.m16n8k16.row.col.f32.bf16.bf16.f32 "
        "{%0,%1,%2,%3}, {%4,%5,%6,%7}, {%8,%9}, {%0,%1,%2,%3};"
        : "+f"(c[0]), "+f"(c[1]), "+f"(c[2]), "+f"(c[3])
        : "r"(a[0]), "r"(a[1]), "r"(a[2]), "r"(a[3]), "r"(b[0]), "r"(b[1]));
}

// split fp32 pair -> packed bf16 hi word + lo word (low half = first arg)
__device__ __forceinline__ void split2(float a, float b, uint32_t& hi, uint32_t& lo) {
    __nv_bfloat16 ah = __float2bfloat16(a), bh = __float2bfloat16(b);
    __nv_bfloat16 al = __float2bfloat16(a - __bfloat162float(ah));
    __nv_bfloat16 bl = __float2bfloat16(b - __bfloat162float(bh));
    hi = (uint32_t)__bfloat16_as_ushort(ah) | ((uint32_t)__bfloat16_as_ushort(bh) << 16);
    lo = (uint32_t)__bfloat16_as_ushort(al) | ((uint32_t)__bfloat16_as_ushort(bl) << 16);
}

// FMA-pipe exp (no MUFU): exp(x) for x <= 0, clamped at -87
__device__ __forceinline__ float fexp(float x) {
    float xc = fmaxf(x, -87.0f);
    float y  = xc * 1.4426950408889634f;
    float t  = y + 12582912.0f;
    float n  = t - 12582912.0f;
    float f  = y - n;
    float p  = 0.0013333558f;
    p = fmaf(p, f, 0.0096181291f);
    p = fmaf(p, f, 0.0555041087f);
    p = fmaf(p, f, 0.2402265069f);
    p = fmaf(p, f, 0.6931471806f);
    p = fmaf(p, f, 1.0f);
    int ni = __float_as_int(t) - 0x4B400000;
    float sc = __int_as_float((ni + 127) << 23);
    return sc * p;
}

__device__ __forceinline__ uint32_t smem_u32(const void* p) {
    uint32_t a;
    asm("{ .reg .u64 t; cvta.to.shared.u64 t, %1; cvt.u32.u64 %0, t; }" : "=r"(a) : "l"(p));
    return a;
}
__device__ __forceinline__ void cpa16(uint32_t dst, const void* src) {
    asm volatile("cp.async.ca.shared.global [%0], [%1], 16;" :: "r"(dst), "l"(src));
}
#define CPA_COMMIT() asm volatile("cp.async.commit_group;" ::: "memory")
#define CPA_WAIT(n)  asm volatile("cp.async.wait_group %0;" :: "n"(n) : "memory")

// ---------------- LayerNorm: one block (128 thr) per row of 512 ----------------
__global__ __launch_bounds__(128) void ln_kernel(
    const float* __restrict__ x, const float* __restrict__ g,
    const float* __restrict__ b, float* __restrict__ out)
{
    int row = blockIdx.x;
    int t = threadIdx.x;
    const float4* xr = (const float4*)(x + (size_t)row * CC);
    float4 v = xr[t];
    float s  = v.x + v.y + v.z + v.w;
    float sq = v.x*v.x + v.y*v.y + v.z*v.z + v.w*v.w;
    #pragma unroll
    for (int o = 16; o; o >>= 1) {
        s  += __shfl_xor_sync(0xffffffffu, s,  o);
        sq += __shfl_xor_sync(0xffffffffu, sq, o);
    }
    __shared__ float rs[4], rq[4];
    int w = t >> 5;
    if ((t & 31) == 0) { rs[w] = s; rq[w] = sq; }
    __syncthreads();
    s  = rs[0] + rs[1] + rs[2] + rs[3];
    sq = rq[0] + rq[1] + rq[2] + rq[3];
    float mean = s * (1.0f / CC);
    float var  = sq * (1.0f / CC) - mean * mean;
    float rstd = rsqrtf(var + 1e-5f);
    float4 gv = ((const float4*)g)[t];
    float4 bv = ((const float4*)b)[t];
    float4 o4;
    o4.x = (v.x - mean) * rstd * gv.x + bv.x;
    o4.y = (v.y - mean) * rstd * gv.y + bv.y;
    o4.z = (v.z - mean) * rstd * gv.z + bv.z;
    o4.w = (v.w - mean) * rstd * gv.w + bv.w;
    ((float4*)(out + (size_t)row * CC))[t] = o4;
}

// ---------------- weight transpose: Wt[n][k] = W[k][n] (fp32) ----------------
__global__ __launch_bounds__(256) void transpose_kernel(
    const float* __restrict__ W, float* __restrict__ Wt, int K, int N)
{
    __shared__ float tile[32][33];
    int n0 = blockIdx.x * 32, k0 = blockIdx.y * 32;
    int tx = threadIdx.x & 31, ty = threadIdx.x >> 5;
    #pragma unroll
    for (int r = 0; r < 32; r += 8)
        tile[ty + r][tx] = W[(size_t)(k0 + ty + r) * N + n0 + tx];
    __syncthreads();
    #pragma unroll
    for (int r = 0; r < 32; r += 8)
        Wt[(size_t)(n0 + ty + r) * K + k0 + tx] = tile[tx][ty + r];
}

// ---------------- tf32 tensor-core GEMM (unchanged) ----------------
#define GP 20
template<int EPI>
__global__ __launch_bounds__(256) void tfgemm_kernel(
    const float* __restrict__ A, const float* __restrict__ Bt,
    const float* __restrict__ bias, const float* __restrict__ resid,
    float* __restrict__ C, int Nn, int K)
{
    __shared__ __align__(16) float As[2][128*GP];
    __shared__ __align__(16) float Bs[2][128*GP];
    int tid = threadIdx.x, lane = tid & 31, wid = tid >> 5;
    int wm = wid & 1, wn = wid >> 1;
    int bm = blockIdx.y * 128, bn = blockIdx.x * 128;

    float acc[4][4][4];
    #pragma unroll
    for (int i = 0; i < 4; i++)
        #pragma unroll
        for (int j = 0; j < 4; j++)
            #pragma unroll
            for (int k = 0; k < 4; k++) acc[i][j][k] = 0.f;

    int lr[2], lc[2];
    #pragma unroll
    for (int l = 0; l < 2; l++) { int idx = tid + l * 256; lr[l] = idx >> 2; lc[l] = (idx & 3) * 4; }
    float4 ra[2], rb[2];

    #pragma unroll
    for (int l = 0; l < 2; l++) {
        ra[l] = *(const float4*)(A  + (size_t)(bm + lr[l]) * K + lc[l]);
        rb[l] = *(const float4*)(Bt + (size_t)(bn + lr[l]) * K + lc[l]);
    }
    #pragma unroll
    for (int l = 0; l < 2; l++) {
        *(float4*)&As[0][lr[l]*GP + lc[l]] = ra[l];
        *(float4*)&Bs[0][lr[l]*GP + lc[l]] = rb[l];
    }
    if (K > 16) {
        #pragma unroll
        for (int l = 0; l < 2; l++) {
            ra[l] = *(const float4*)(A  + (size_t)(bm + lr[l]) * K + 16 + lc[l]);
            rb[l] = *(const float4*)(Bt + (size_t)(bn + lr[l]) * K + 16 + lc[l]);
        }
    }
    __syncthreads();

    int nst = K / 16, cur = 0;
    for (int t = 0; t < nst; t++) {
        const float* Ac = &As[cur][0];
        const float* Bc = &Bs[cur][0];
        #pragma unroll
        for (int ks = 0; ks < 2; ks++) {
            int k0 = ks * 8 + (lane & 3);
            uint32_t af[4][4], bfr[4][2];
            #pragma unroll
            for (int mf = 0; mf < 4; mf++) {
                int r = wm * 64 + mf * 16 + (lane >> 2);
                af[mf][0] = __float_as_uint(Ac[r*GP + k0]);
                af[mf][1] = __float_as_uint(Ac[(r+8)*GP + k0]);
                af[mf][2] = __float_as_uint(Ac[r*GP + k0 + 4]);
                af[mf][3] = __float_as_uint(Ac[(r+8)*GP + k0 + 4]);
            }
            #pragma unroll
            for (int nf = 0; nf < 4; nf++) {
                int n = wn * 32 + nf * 8 + (lane >> 2);
                bfr[nf][0] = __float_as_uint(Bc[n*GP + k0]);
                bfr[nf][1] = __float_as_uint(Bc[n*GP + k0 + 4]);
            }
            #pragma unroll
            for (int mf = 0; mf < 4; mf++)
                #pragma unroll
                for (int nf = 0; nf < 4; nf++)
                    mma_tf32(acc[mf][nf], af[mf], bfr[nf]);
        }
        if (t + 1 < nst) {
            int nb = 1 ^ cur;
            #pragma unroll
            for (int l = 0; l < 2; l++) {
                *(float4*)&As[nb][lr[l]*GP + lc[l]] = ra[l];
                *(float4*)&Bs[nb][lr[l]*GP + lc[l]] = rb[l];
            }
            if (t + 2 < nst) {
                int k0 = (t + 2) * 16;
                #pragma unroll
                for (int l = 0; l < 2; l++) {
                    ra[l] = *(const float4*)(A  + (size_t)(bm + lr[l]) * K + k0 + lc[l]);
                    rb[l] = *(const float4*)(Bt + (size_t)(bn + lr[l]) * K + k0 + lc[l]);
                }
            }
        }
        __syncthreads();
        cur ^= 1;
    }

    int mrow = bm + wm * 64 + (lane >> 2);
    int nc0  = bn + wn * 32 + (lane & 3) * 2;
    #pragma unroll
    for (int nf = 0; nf < 4; nf++) {
        int nc = nc0 + nf * 8;
        float b0 = bias[nc], b1 = bias[nc + 1];
        #pragma unroll
        for (int mf = 0; mf < 4; mf++) {
            #pragma unroll
            for (int half = 0; half < 2; half++) {
                int r = mrow + mf * 16 + half * 8;
                float v0 = acc[mf][nf][half*2 + 0] + b0;
                float v1 = acc[mf][nf][half*2 + 1] + b1;
                if (EPI == 1) { v0 = gelu_exact(v0); v1 = gelu_exact(v1); }
                if (EPI == 2) {
                    float2 rr = *(const float2*)(resid + (size_t)r * Nn + nc);
                    v0 += rr.x; v1 += rr.y;
                }
                *(float2*)(C + (size_t)r * Nn + nc) = make_float2(v0, v1);
            }
        }
    }
}

// ---------------- rearrange: effective Q (fp32) + pre-split bf16 K, V ----------------
// thread handles key pair (n0, n0+1) x 8 dims. 32 bh x 768 pairs x 8 dblk = 196608 thr.
__global__ __launch_bounds__(256) void rearrange_kernel()
{
    int flat = blockIdx.x * 256 + threadIdx.x;
    int db = flat & 7;
    int m  = (flat >> 3) % 768;
    int bh = (flat >> 3) / 768;
    int h = bh & 7, b = bh >> 3;
    int n0 = 2 * m;
    int d0 = db * 8;
    int c4 = (h * 64 + d0) >> 2;     // float4 col in 1536-wide row
    const float4* qkv4 = (const float4*)g_qkv;

    #pragma unroll
    for (int kk = 0; kk < 2; kk++) {
        int n = n0 + kk;
        size_t row = (size_t)(b * NNq + n) * 384;
        // ---- Q (shift folded, scaled) -> g_qe fp32 ----
        float4 qa = qkv4[row + c4];
        float4 qb = qkv4[row + c4 + 1];
        if (n >= 512) {
            size_t r2 = row - (size_t)512 * 384;
            float4 t = qkv4[r2 + c4], t2 = qkv4[r2 + c4 + 1];
            qa.x += 0.5f*t.x; qa.y += 0.5f*t.y; qa.z += 0.5f*t.z; qa.w += 0.5f*t.w;
            qb.x += 0.5f*t2.x; qb.y += 0.5f*t2.y; qb.z += 0.5f*t2.z; qb.w += 0.5f*t2.w;
        }
        if (n >= 1024) {
            size_t r2 = row - (size_t)1024 * 384;
            float4 t = qkv4[r2 + c4], t2 = qkv4[r2 + c4 + 1];
            qa.x += 0.25f*t.x; qa.y += 0.25f*t.y; qa.z += 0.25f*t.z; qa.w += 0.25f*t.w;
            qb.x += 0.25f*t2.x; qb.y += 0.25f*t2.y; qb.z += 0.25f*t2.z; qb.w += 0.25f*t2.w;
        }
        qa.x *= 0.125f; qa.y *= 0.125f; qa.z *= 0.125f; qa.w *= 0.125f;
        qb.x *= 0.125f; qb.y *= 0.125f; qb.z *= 0.125f; qb.w *= 0.125f;
        float* qo = g_qe + ((size_t)bh * NNq + n) * DD + d0;
        *(float4*)qo = qa;
        *(float4*)(qo + 4) = qb;

        // ---- K -> split hi/lo, [bh][key][dpair] ----
        float4 k0v = qkv4[row + 128 + c4];
        float4 k1v = qkv4[row + 128 + c4 + 1];
        uint32_t hw0, lw0, hw1, lw1, hw2, lw2, hw3, lw3;
        split2(k0v.x, k0v.y, hw0, lw0);
        split2(k0v.z, k0v.w, hw1, lw1);
        split2(k1v.x, k1v.y, hw2, lw2);
        split2(k1v.z, k1v.w, hw3, lw3);
        size_t kw = ((size_t)bh * NNq + n) * 32 + db * 4;
        *(uint4*)&g_kh[kw] = make_uint4(hw0, hw1, hw2, hw3);
        *(uint4*)&g_kl[kw] = make_uint4(lw0, lw1, lw2, lw3);
    }

    // ---- V -> split hi/lo, d-major [bh][ktile][d][keypair]; low = key n0 ----
    size_t row0 = (size_t)(b * NNq + n0) * 384;
    size_t row1 = (size_t)(b * NNq + n0 + 1) * 384;
    float4 v0a = qkv4[row0 + 256 + c4], v0b = qkv4[row0 + 256 + c4 + 1];
    float4 v1a = qkv4[row1 + 256 + c4], v1b = qkv4[row1 + 256 + c4 + 1];
    float va[8] = {v0a.x, v0a.y, v0a.z, v0a.w, v0b.x, v0b.y, v0b.z, v0b.w};
    float vb[8] = {v1a.x, v1a.y, v1a.z, v1a.w, v1b.x, v1b.y, v1b.z, v1b.w};
    int kt = n0 >> 6, vm = m & 31;
    size_t vbase = (((size_t)bh * NT + kt) * 64 + d0) * 32 + vm;
    #pragma unroll
    for (int j = 0; j < 8; j++) {
        uint32_t hi, lo;
        split2(va[j], vb[j], hi, lo);
        g_vh[vbase + (size_t)j * 32] = hi;
        g_vl[vbase + (size_t)j * 32] = lo;
    }
}

// ---------------- flash attention: bf16x3 MMA, reg-Q/P, cp.async double buffer ----------------
// buffer layout (words): KH 0, KL 2304, VH 4608, VL 6912; buffer = 9216 words (36864 B), x2
#define AQP 36
#define ABUF_W 9216
#define ATTN_SMEM (2*ABUF_W*4)   // 73728 B

__device__ __forceinline__ void attn_copy_tile(
    uint32_t sbase_bytes, int bh, int kt, int tid)
{
    int r = tid >> 2, q = tid & 3;
    uint32_t o = (uint32_t)(r * AQP + q * 8) * 4;
    const uint32_t* khp = g_kh + ((size_t)bh * NNq + (size_t)kt * 64 + r) * 32 + q * 8;
    const uint32_t* klp = g_kl + ((size_t)bh * NNq + (size_t)kt * 64 + r) * 32 + q * 8;
    const uint32_t* vhp = g_vh + (((size_t)bh * NT + kt) * 64 + r) * 32 + q * 8;
    const uint32_t* vlp = g_vl + (((size_t)bh * NT + kt) * 64 + r) * 32 + q * 8;
    cpa16(sbase_bytes + o,          khp);
    cpa16(sbase_bytes + o + 16,     khp + 4);
    cpa16(sbase_bytes + 9216  + o,      klp);
    cpa16(sbase_bytes + 9216  + o + 16, klp + 4);
    cpa16(sbase_bytes + 18432 + o,      vhp);
    cpa16(sbase_bytes + 18432 + o + 16, vhp + 4);
    cpa16(sbase_bytes + 27648 + o,      vlp);
    cpa16(sbase_bytes + 27648 + o + 16, vlp + 4);
}

__global__ __launch_bounds__(256, 2) void attn_kernel(
    const float* __restrict__ x, float* __restrict__ x2)
{
    extern __shared__ __align__(16) uint32_t smw[];
    uint32_t sb = smem_u32(smw);

    int tid = threadIdx.x, lane = tid & 31, wid = tid >> 5;
    int bh = blockIdx.y;
    int q0 = blockIdx.x * 128;
    const float* Qg = g_qe + (size_t)bh * NNq * DD + (size_t)q0 * DD;

    int rbase = wid * 16;
    int lr4 = lane >> 2, lc4 = lane & 3;

    // prologue: tile 0 -> buf 0 (async)
    attn_copy_tile(sb, bh, 0, tid);
    CPA_COMMIT();

    // ---- Q fragments: loaded from gmem ONCE, live in registers all 24 tiles ----
    uint32_t qH[4][4], qL[4][4];
    {
        const float* Qr0 = Qg + (size_t)(rbase + lr4) * DD;
        const float* Qr1 = Qr0 + 8 * DD;
        #pragma unroll
        for (int ks = 0; ks < 4; ks++) {
            int d0 = ks * 16 + 2 * lc4;
            float2 a = *(const float2*)(Qr0 + d0);
            float2 b = *(const float2*)(Qr1 + d0);
            float2 c = *(const float2*)(Qr0 + d0 + 8);
            float2 d = *(const float2*)(Qr1 + d0 + 8);
            split2(a.x, a.y, qH[ks][0], qL[ks][0]);
            split2(b.x, b.y, qH[ks][1], qL[ks][1]);
            split2(c.x, c.y, qH[ks][2], qL[ks][2]);
            split2(d.x, d.y, qH[ks][3], qL[ks][3]);
        }
    }

    float m_run[2] = {-3.0e38f, -3.0e38f};
    float l_run[2] = {0.f, 0.f};
    float oac[8][4];
    #pragma unroll
    for (int nf = 0; nf < 8; nf++)
        #pragma unroll
        for (int k = 0; k < 4; k++) oac[nf][k] = 0.f;

    int cur = 0;
    for (int kt = 0; kt < NT; kt++) {
        __syncthreads();   // everyone done reading the buffer about to be overwritten
        if (kt + 1 < NT) {
            attn_copy_tile(sb + (1 ^ cur) * 36864u, bh, kt + 1, tid);
            CPA_COMMIT();
            CPA_WAIT(1);   // tile kt's group complete; kt+1 stays in flight
        } else {
            CPA_WAIT(0);
        }
        __syncthreads();   // all threads' copies of tile kt visible

        const uint32_t* KH = smw + cur * ABUF_W;
        const uint32_t* KL = KH + 2304;
        const uint32_t* VH = KH + 4608;
        const uint32_t* VL = KH + 6912;

        // ---- S = Q'K^T (bf16x3), Q frags from registers ----
        float c[8][4];
        #pragma unroll
        for (int nf = 0; nf < 8; nf++)
            #pragma unroll
            for (int k = 0; k < 4; k++) c[nf][k] = 0.f;
        #pragma unroll
        for (int ks = 0; ks < 4; ks++) {
            #pragma unroll
            for (int nf = 0; nf < 8; nf++) {
                uint32_t bw = (nf * 8 + lr4) * AQP + ks * 8 + lc4;
                uint32_t bH[2] = {KH[bw], KH[bw + 4]};
                uint32_t bL[2] = {KL[bw], KL[bw + 4]};
                mma_bf16(c[nf], qH[ks], bH);
                mma_bf16(c[nf], qH[ks], bL);
                mma_bf16(c[nf], qL[ks], bH);
            }
        }

        // ---- online softmax per row-half, exp in place (P stays in c) ----
        #pragma unroll
        for (int h = 0; h < 2; h++) {
            int ci = h * 2;
            float mx = -3.0e38f;
            #pragma unroll
            for (int nf = 0; nf < 8; nf++)
                mx = fmaxf(mx, fmaxf(c[nf][ci], c[nf][ci + 1]));
            mx = fmaxf(mx, __shfl_xor_sync(0xffffffffu, mx, 1));
            mx = fmaxf(mx, __shfl_xor_sync(0xffffffffu, mx, 2));
            float mnew = fmaxf(m_run[h], mx);
            float corr = fexp(m_run[h] - mnew);
            float sum = 0.f;
            #pragma unroll
            for (int nf = 0; nf < 8; nf++) {
                float p0 = fexp(c[nf][ci]     - mnew);
                float p1 = fexp(c[nf][ci + 1] - mnew);
                c[nf][ci] = p0; c[nf][ci + 1] = p1;
                sum += p0 + p1;
            }
            sum += __shfl_xor_sync(0xffffffffu, sum, 1);
            sum += __shfl_xor_sync(0xffffffffu, sum, 2);
            l_run[h] = l_run[h] * corr + sum;
            m_run[h] = mnew;
            #pragma unroll
            for (int nf = 0; nf < 8; nf++) {
                oac[nf][ci]     *= corr;
                oac[nf][ci + 1] *= corr;
            }
        }

        // ---- O += P V (bf16x3): A-fragments from c registers ----
        #pragma unroll
        for (int j = 0; j < 4; j++) {
            uint32_t aH[4], aL[4];
            split2(c[2*j][0],     c[2*j][1],     aH[0], aL[0]);
            split2(c[2*j][2],     c[2*j][3],     aH[1], aL[1]);
            split2(c[2*j + 1][0], c[2*j + 1][1], aH[2], aL[2]);
            split2(c[2*j + 1][2], c[2*j + 1][3], aH[3], aL[3]);
            #pragma unroll
            for (int nf = 0; nf < 8; nf++) {
                uint32_t bw = (nf * 8 + lr4) * AQP + j * 8 + lc4;
                uint32_t bH[2] = {VH[bw], VH[bw + 4]};
                uint32_t bL[2] = {VL[bw], VL[bw + 4]};
                mma_bf16(oac[nf], aH, bH);
                mma_bf16(oac[nf], aH, bL);
                mma_bf16(oac[nf], aL, bH);
            }
        }
        cur ^= 1;
    }

    // ---- epilogue: x2 = x + O / l ----
    int b = bh >> 3, hd = bh & 7;
    #pragma unroll
    for (int h = 0; h < 2; h++) {
        float inv = 1.0f / l_run[h];
        int n = q0 + rbase + lr4 + h * 8;
        #pragma unroll
        for (int nf = 0; nf < 8; nf++) {
            int d = nf * 8 + lc4 * 2;
            size_t off = ((size_t)(b * NNq + n)) * CC + hd * 64 + d;
            float2 xr = *(const float2*)(x + off);
            *(float2*)(x2 + off) = make_float2(
                xr.x + oac[nf][h*2]     * inv,
                xr.y + oac[nf][h*2 + 1] * inv);
        }
    }
}

// ---------------- host ----------------
extern "C" void kernel_launch(void* const* d_in, const int* in_sizes, int n_in,
                              void* d_out, int out_size)
{
    const float* x     = (const float*)d_in[0];
    const float* ln1_g = (const float*)d_in[1];
    const float* ln1_b = (const float*)d_in[2];
    const float* qkv_w = (const float*)d_in[3];
    const float* qkv_b = (const float*)d_in[4];
    const float* ln2_g = (const float*)d_in[5];
    const float* ln2_b = (const float*)d_in[6];
    const float* fc1_w = (const float*)d_in[7];
    const float* fc1_b = (const float*)d_in[8];
    const float* fc2_w = (const float*)d_in[9];
    const float* fc2_b = (const float*)d_in[10];
    float* out = (float*)d_out;

    float *p_h, *p_qkv, *p_x2, *p_h2, *p_act, *p_wq, *p_w1, *p_w2;
    cudaGetSymbolAddress((void**)&p_h,   g_h);
    cudaGetSymbolAddress((void**)&p_qkv, g_qkv);
    cudaGetSymbolAddress((void**)&p_x2,  g_x2);
    cudaGetSymbolAddress((void**)&p_h2,  g_h2);
    cudaGetSymbolAddress((void**)&p_act, g_act);
    cudaGetSymbolAddress((void**)&p_wq,  g_wq);
    cudaGetSymbolAddress((void**)&p_w1,  g_w1);
    cudaGetSymbolAddress((void**)&p_w2,  g_w2);

    cudaFuncSetAttribute(attn_kernel, cudaFuncAttributeMaxDynamicSharedMemorySize, ATTN_SMEM);

    // weight transposes -> [N][K] fp32
    transpose_kernel<<<dim3(1536/32, 512/32), 256>>>(qkv_w, p_wq, 512, 1536);
    transpose_kernel<<<dim3(1024/32, 512/32), 256>>>(fc1_w, p_w1, 512, 1024);
    transpose_kernel<<<dim3(512/32, 1024/32), 256>>>(fc2_w, p_w2, 1024, 512);

    // 1. LN1
    ln_kernel<<<ROWS, 128>>>(x, ln1_g, ln1_b, p_h);
    // 2. QKV projection (tf32 tensor cores)
    tfgemm_kernel<0><<<dim3(1536/128, ROWS/128), 256>>>(p_h, p_wq, qkv_b, nullptr, p_qkv, 1536, 512);
    // 3. effective-Q + pre-split bf16 K/V
    rearrange_kernel<<<(32*768*8)/256, 256>>>();
    // 4. flash attention (bf16x3, cp.async double buffer) + residual into x2
    attn_kernel<<<dim3(NNq/128, BB*HH), 256, ATTN_SMEM>>>(x, p_x2);
    // 5. LN2
    ln_kernel<<<ROWS, 128>>>(p_x2, ln2_g, ln2_b, p_h2);
    // 6. FC1 + GELU (tf32)
    tfgemm_kernel<1><<<dim3(HID/128, ROWS/128), 256>>>(p_h2, p_w1, fc1_b, nullptr, p_act, HID, 512);
    // 7. FC2 + residual (tf32) -> out
    tfgemm_kernel<2><<<dim3(CC/128, ROWS/128), 256>>>(p_act, p_w2, fc2_b, p_x2, out, CC, 1024);
}